// round 1
// baseline (speedup 1.0000x reference)
#include <cuda_runtime.h>
#include <cstdint>
#include <math.h>

#define H     1024
#define BATCH 64
#define TENC  128
#define TDEC  64
#define VOCAB 32000
#define DEMB  512

// ---------------- scratch (static device globals; no allocation) ----------------
__device__ float g_Xe[(size_t)TENC * BATCH * DEMB];        // 16.8 MB  gathered enc embeddings
__device__ float g_Xi[(size_t)TENC * BATCH * 3 * H];       // 100.7 MB gi for encoder (all t)
__device__ float g_Xw[(size_t)TDEC * BATCH * DEMB];        // 8.4 MB   gathered dec word embeddings
__device__ float g_Xd[(size_t)TDEC * BATCH * 3 * H];       // 50.3 MB  gi word-part for decoder
__device__ float g_ctx[(size_t)BATCH * 3 * H];             // ctx-part of gi (constant over t)
__device__ float g_h0[(size_t)BATCH * H];
__device__ float g_h1[(size_t)BATCH * H];
__device__ float g_hd0[(size_t)BATCH * H];
__device__ float g_hd1[(size_t)BATCH * H];
__device__ float g_st[(size_t)TDEC * BATCH * H];           // 16.8 MB  decoder states (t*B+b, H)

// ---------------- helpers ----------------
__device__ __forceinline__ uint32_t f2tf32(float f) {
    uint32_t r;
    asm("cvt.rna.tf32.f32 %0, %1;" : "=r"(r) : "f"(f));
    return r;
}

__device__ __forceinline__ void cvt_store4(uint32_t* dst, float4 v) {
    dst[0] = f2tf32(v.x); dst[1] = f2tf32(v.y);
    dst[2] = f2tf32(v.z); dst[3] = f2tf32(v.w);
}

__device__ __forceinline__ void mma_tf32(float* c, const uint32_t* a, const uint32_t* b) {
    asm volatile(
        "mma.sync.aligned.m16n8k8.row.col.f32.tf32.tf32.f32 "
        "{%0,%1,%2,%3}, {%4,%5,%6,%7}, {%8,%9}, {%0,%1,%2,%3};\n"
        : "+f"(c[0]), "+f"(c[1]), "+f"(c[2]), "+f"(c[3])
        : "r"(a[0]), "r"(a[1]), "r"(a[2]), "r"(a[3]), "r"(b[0]), "r"(b[1]));
}

// ---------------- embedding gathers ----------------
__global__ void embed_enc_k(const int* __restrict__ x, const float* __restrict__ emb,
                            float* __restrict__ Xe) {
    int row = blockIdx.x;                 // row = t*BATCH + b
    int t = row >> 6, b = row & 63;
    int tok = x[b * TENC + t];
    const float4* src = (const float4*)(emb + (size_t)tok * DEMB);
    float4* dst = (float4*)(Xe + (size_t)row * DEMB);
    dst[threadIdx.x] = src[threadIdx.x];  // 128 threads * float4 = 512
}

__global__ void embed_dec_k(const int* __restrict__ labels, const int* __restrict__ bos,
                            const float* __restrict__ emb, float* __restrict__ Xw) {
    int row = blockIdx.x;                 // row = t*BATCH + b
    int t = row >> 6, b = row & 63;
    int tok = (t == 0) ? bos[0] : labels[b * TDEC + t - 1];
    const float4* src = (const float4*)(emb + (size_t)tok * DEMB);
    float4* dst = (float4*)(Xw + (size_t)row * DEMB);
    dst[threadIdx.x] = src[threadIdx.x];
}

__global__ void init_h_k(float* __restrict__ h, const float* __restrict__ init_row) {
    int b = blockIdx.x, u = threadIdx.x;  // blockDim = H
    h[b * H + u] = init_row ? init_row[u] : 0.0f;
}

// ---------------- generic TF32 GEMM: C[m,n] = sum_k A[m,k]*W[n*ldw+koff+k] + bias[n] ----------------
// BM=128, BN=128, BK=16; 8 warps (4x2), warp tile 32x64; mma m16n8k8.
__global__ __launch_bounds__(256, 2)
void gemm_tf32_k(const float* __restrict__ A, int lda,
                 const float* __restrict__ W, int ldw, int koff,
                 const float* __restrict__ bias,
                 float* __restrict__ C,
                 int M, int N, int K, int trans_out) {
    __shared__ uint32_t As[128][20];
    __shared__ uint32_t Bs[128][20];

    const int m0 = blockIdx.x * 128, n0 = blockIdx.y * 128;
    const int tid = threadIdx.x, lane = tid & 31, wid = tid >> 5;
    const int wr = wid >> 1, wc = wid & 1;
    const int g = lane >> 2, tg = lane & 3;

    float acc[2][8][4];
#pragma unroll
    for (int ms = 0; ms < 2; ms++)
#pragma unroll
        for (int ns = 0; ns < 8; ns++)
#pragma unroll
            for (int i = 0; i < 4; i++) acc[ms][ns][i] = 0.0f;

    const int lrow = tid >> 1, lcol = (tid & 1) * 8;
    const float* Ap = A + (size_t)(m0 + lrow) * lda + lcol;
    const float* Wp = W + (size_t)(n0 + lrow) * ldw + koff + lcol;
    const bool aok = (m0 + lrow) < M;

    for (int k0 = 0; k0 < K; k0 += 16) {
        if (aok) {
            float4 v0 = *(const float4*)(Ap + k0);
            float4 v1 = *(const float4*)(Ap + k0 + 4);
            cvt_store4(&As[lrow][lcol], v0);
            cvt_store4(&As[lrow][lcol + 4], v1);
        } else {
#pragma unroll
            for (int i = 0; i < 8; i++) As[lrow][lcol + i] = 0u;
        }
        {
            float4 w0 = *(const float4*)(Wp + k0);
            float4 w1 = *(const float4*)(Wp + k0 + 4);
            cvt_store4(&Bs[lrow][lcol], w0);
            cvt_store4(&Bs[lrow][lcol + 4], w1);
        }
        __syncthreads();

#pragma unroll
        for (int kk = 0; kk < 16; kk += 8) {
            uint32_t a[2][4], b[8][2];
#pragma unroll
            for (int ms = 0; ms < 2; ms++) {
                int r0 = wr * 32 + ms * 16 + g;
                a[ms][0] = As[r0][kk + tg];
                a[ms][1] = As[r0 + 8][kk + tg];
                a[ms][2] = As[r0][kk + tg + 4];
                a[ms][3] = As[r0 + 8][kk + tg + 4];
            }
#pragma unroll
            for (int ns = 0; ns < 8; ns++) {
                int br = wc * 64 + ns * 8 + g;
                b[ns][0] = Bs[br][kk + tg];
                b[ns][1] = Bs[br][kk + tg + 4];
            }
#pragma unroll
            for (int ms = 0; ms < 2; ms++)
#pragma unroll
                for (int ns = 0; ns < 8; ns++)
                    mma_tf32(acc[ms][ns], a[ms], b[ns]);
        }
        __syncthreads();
    }

#pragma unroll
    for (int ms = 0; ms < 2; ms++)
#pragma unroll
        for (int ns = 0; ns < 8; ns++) {
            int row = m0 + wr * 32 + ms * 16 + g;
            int col = n0 + wc * 64 + ns * 8 + 2 * tg;
            float b0 = bias ? bias[col] : 0.0f;
            float b1 = bias ? bias[col + 1] : 0.0f;
#pragma unroll
            for (int h2 = 0; h2 < 2; h2++) {
                int r = row + h2 * 8;
                if (r < M) {
                    size_t idx;
                    if (trans_out) {  // rows are (t*BATCH+b); store out[b][t][col]
                        int bb = r & 63, tt = r >> 6;
                        idx = ((size_t)bb * TDEC + tt) * (size_t)N + col;
                    } else {
                        idx = (size_t)r * (size_t)N + col;
                    }
                    C[idx]     = acc[ms][ns][h2 * 2 + 0] + b0;
                    C[idx + 1] = acc[ms][ns][h2 * 2 + 1] + b1;
                }
            }
        }
}

// ---------------- fused GRU step: gh = h @ Whh^T (+bhh) + gates ----------------
// 64 CTAs, each handles 16 hidden units (48 Whh rows: r block, z block, n block).
// 4 warps; warp w covers batch rows [w*16, w*16+16); 6 n-tiles of 8 over the 48 cols.
template <bool DEC>
__global__ __launch_bounds__(128)
void gru_step_k(const float* __restrict__ h_in, float* __restrict__ h_out,
                const float* __restrict__ Whh, const float* __restrict__ bhh,
                const float* __restrict__ gi_t, const float* __restrict__ ctxW,
                float* __restrict__ st_out) {
    __shared__ uint32_t As[64][20];  // h tile (64 x 16)
    __shared__ uint32_t Bs[48][20];  // Whh tile (48 x 16)

    const int u0 = blockIdx.x * 16;
    const int tid = threadIdx.x, lane = tid & 31, w = tid >> 5;
    const int g = lane >> 2, tg = lane & 3;

    float acc[6][4];
#pragma unroll
    for (int j = 0; j < 6; j++)
#pragma unroll
        for (int i = 0; i < 4; i++) acc[j][i] = 0.0f;

    const int lrow = tid >> 1, lcol = (tid & 1) * 8;
    const float* Ap = h_in + (size_t)lrow * H + lcol;
    const float* Bp = nullptr;
    if (tid < 96) {
        int br = lrow;               // 0..47
        int gate = br >> 4, iu = br & 15;
        Bp = Whh + (size_t)(gate * H + u0 + iu) * H + lcol;
    }

    for (int k0 = 0; k0 < H; k0 += 16) {
        {
            float4 v0 = *(const float4*)(Ap + k0);
            float4 v1 = *(const float4*)(Ap + k0 + 4);
            cvt_store4(&As[lrow][lcol], v0);
            cvt_store4(&As[lrow][lcol + 4], v1);
        }
        if (tid < 96) {
            float4 w0 = *(const float4*)(Bp + k0);
            float4 w1 = *(const float4*)(Bp + k0 + 4);
            cvt_store4(&Bs[lrow][lcol], w0);
            cvt_store4(&Bs[lrow][lcol + 4], w1);
        }
        __syncthreads();

#pragma unroll
        for (int kk = 0; kk < 16; kk += 8) {
            uint32_t a[4], b[6][2];
            int m0 = w * 16;
            a[0] = As[m0 + g][kk + tg];
            a[1] = As[m0 + g + 8][kk + tg];
            a[2] = As[m0 + g][kk + tg + 4];
            a[3] = As[m0 + g + 8][kk + tg + 4];
#pragma unroll
            for (int jt = 0; jt < 6; jt++) {
                b[jt][0] = Bs[jt * 8 + g][kk + tg];
                b[jt][1] = Bs[jt * 8 + g][kk + tg + 4];
            }
#pragma unroll
            for (int jt = 0; jt < 6; jt++) mma_tf32(acc[jt], a, b[jt]);
        }
        __syncthreads();
    }

    // gate fusion. C col within 48 = 8*jt + 2*tg + (i&1); gate = col/16; u_local = col%16.
    // For this thread: jt = 2*gate + half, u_local = half*8 + 2*tg + (i&1).
    const int m0 = w * 16;
#pragma unroll
    for (int half = 0; half < 2; half++) {
#pragma unroll
        for (int i = 0; i < 4; i++) {
            int dl = i & 1, ro = (i >> 1) * 8;
            int b = m0 + g + ro;                 // batch row
            int u = u0 + half * 8 + 2 * tg + dl; // hidden unit
            float aR = acc[0 + half][i];
            float aZ = acc[2 + half][i];
            float aN = acc[4 + half][i];
            const float* gi = gi_t + (size_t)b * 3 * H;
            float gr = gi[u], gz = gi[H + u], gn = gi[2 * H + u];
            if (DEC) {
                const float* cw = ctxW + (size_t)b * 3 * H;
                gr += cw[u]; gz += cw[H + u]; gn += cw[2 * H + u];
            }
            float rr = 1.0f / (1.0f + expf(-(gr + aR + bhh[u])));
            float zz = 1.0f / (1.0f + expf(-(gz + aZ + bhh[H + u])));
            float nn = tanhf(gn + rr * (aN + bhh[2 * H + u]));
            float hn = (1.0f - zz) * nn + zz * h_in[(size_t)b * H + u];
            h_out[(size_t)b * H + u] = hn;
            if (DEC) st_out[(size_t)b * H + u] = hn;
        }
    }
}

// ---------------- host orchestration ----------------
extern "C" void kernel_launch(void* const* d_in, const int* in_sizes, int n_in,
                              void* d_out, int out_size) {
    const int*   x        = (const int*)d_in[0];
    const int*   labels   = (const int*)d_in[1];
    const int*   bos      = (const int*)d_in[2];
    const float* enc_emb  = (const float*)d_in[3];
    const float* enc_Wih  = (const float*)d_in[4];
    const float* enc_Whh  = (const float*)d_in[5];
    const float* enc_bih  = (const float*)d_in[6];
    const float* enc_bhh  = (const float*)d_in[7];
    const float* dec_emb  = (const float*)d_in[8];
    const float* dec_Wih  = (const float*)d_in[9];
    const float* dec_Whh  = (const float*)d_in[10];
    const float* dec_bih  = (const float*)d_in[11];
    const float* dec_bhh  = (const float*)d_in[12];
    const float* dec_init = (const float*)d_in[13];
    const float* lin_W    = (const float*)d_in[14];
    const float* lin_b    = (const float*)d_in[15];
    float*       out      = (float*)d_out;

    float *Xe, *Xi, *Xw, *Xd, *ctx, *h0, *h1, *hd0, *hd1, *st;
    cudaGetSymbolAddress((void**)&Xe, g_Xe);
    cudaGetSymbolAddress((void**)&Xi, g_Xi);
    cudaGetSymbolAddress((void**)&Xw, g_Xw);
    cudaGetSymbolAddress((void**)&Xd, g_Xd);
    cudaGetSymbolAddress((void**)&ctx, g_ctx);
    cudaGetSymbolAddress((void**)&h0, g_h0);
    cudaGetSymbolAddress((void**)&h1, g_h1);
    cudaGetSymbolAddress((void**)&hd0, g_hd0);
    cudaGetSymbolAddress((void**)&hd1, g_hd1);
    cudaGetSymbolAddress((void**)&st, g_st);

    // ---- encoder ----
    embed_enc_k<<<TENC * BATCH, 128>>>(x, enc_emb, Xe);
    // Xi = Xe @ enc_Wih^T + enc_bih   (8192 x 3072, K=512)
    gemm_tf32_k<<<dim3(64, 24), 256>>>(Xe, DEMB, enc_Wih, DEMB, 0, enc_bih, Xi,
                                       TENC * BATCH, 3 * H, DEMB, 0);
    init_h_k<<<BATCH, H>>>(h0, nullptr);
    for (int t = 0; t < TENC; t++) {
        float* hi = (t & 1) ? h1 : h0;
        float* ho = (t & 1) ? h0 : h1;
        gru_step_k<false><<<H / 16, 128>>>(hi, ho, enc_Whh, enc_bhh,
                                           Xi + (size_t)t * BATCH * 3 * H, nullptr, nullptr);
    }
    float* efin = h0;  // TENC even -> final state lands back in h0

    // ---- decoder precompute ----
    embed_dec_k<<<TDEC * BATCH, 128>>>(labels, bos, dec_emb, Xw);
    // Xd = words @ dec_Wih[:, :512]^T + dec_bih   (4096 x 3072, K=512, ldw=1536)
    gemm_tf32_k<<<dim3(32, 24), 256>>>(Xw, DEMB, dec_Wih, DEMB + H, 0, dec_bih, Xd,
                                       TDEC * BATCH, 3 * H, DEMB, 0);
    // ctx = e_final @ dec_Wih[:, 512:]^T           (64 x 3072, K=1024)
    gemm_tf32_k<<<dim3(1, 24), 256>>>(efin, H, dec_Wih, DEMB + H, DEMB, nullptr, ctx,
                                      BATCH, 3 * H, H, 0);
    init_h_k<<<BATCH, H>>>(hd0, dec_init);
    for (int t = 0; t < TDEC; t++) {
        float* hi = (t & 1) ? hd1 : hd0;
        float* ho = (t & 1) ? hd0 : hd1;
        gru_step_k<true><<<H / 16, 128>>>(hi, ho, dec_Whh, dec_bhh,
                                          Xd + (size_t)t * BATCH * 3 * H, ctx,
                                          st + (size_t)t * BATCH * H);
    }

    // ---- logits: out[b][t][v] = states[(t,b),:] @ lin_W^T + lin_b ----
    gemm_tf32_k<<<dim3(32, 250), 256>>>(st, H, lin_W, H, 0, lin_b, out,
                                        TDEC * BATCH, VOCAB, H, 1);
}

// round 2
// speedup vs baseline: 1.8298x; 1.8298x over previous
#include <cuda_runtime.h>
#include <cstdint>
#include <math.h>

#define H     1024
#define BATCH 64
#define TENC  128
#define TDEC  64
#define VOCAB 32000
#define DEMB  512
#define NCTA  64

#define WSH_STRIDE 1028
#define ASH_STRIDE 36
#define GSH_STRIDE 52
// smem words: Wsh 48*1028 = 49344 ; union(Ash 2*64*36=4608, Gsh 2*64*52=6656)
#define SMEM_WORDS (48 * WSH_STRIDE + 2 * 64 * GSH_STRIDE)
#define SMEM_BYTES (SMEM_WORDS * 4)

// ---------------- scratch ----------------
__device__ float g_Xe[(size_t)TENC * BATCH * DEMB];
__device__ float g_Xi[(size_t)TENC * BATCH * 3 * H];
__device__ float g_Xw[(size_t)TDEC * BATCH * DEMB];
__device__ float g_Xd[(size_t)TDEC * BATCH * 3 * H];
__device__ float g_ctx[(size_t)BATCH * 3 * H];
__device__ float g_h0[(size_t)BATCH * H];
__device__ float g_h1[(size_t)BATCH * H];
__device__ float g_hd0[(size_t)BATCH * H];
__device__ float g_hd1[(size_t)BATCH * H];
__device__ float g_st[(size_t)TDEC * BATCH * H];
__device__ unsigned g_bar_cnt;
__device__ unsigned g_bar_gen;

// ---------------- helpers ----------------
__device__ __forceinline__ uint32_t f2tf32(float f) {
    uint32_t r;
    asm("cvt.rna.tf32.f32 %0, %1;" : "=r"(r) : "f"(f));
    return r;
}
__device__ __forceinline__ void cvt_store4(uint32_t* dst, float4 v) {
    dst[0] = f2tf32(v.x); dst[1] = f2tf32(v.y);
    dst[2] = f2tf32(v.z); dst[3] = f2tf32(v.w);
}
__device__ __forceinline__ void mma_tf32(float* c, const uint32_t* a, const uint32_t* b) {
    asm volatile(
        "mma.sync.aligned.m16n8k8.row.col.f32.tf32.tf32.f32 "
        "{%0,%1,%2,%3}, {%4,%5,%6,%7}, {%8,%9}, {%0,%1,%2,%3};\n"
        : "+f"(c[0]), "+f"(c[1]), "+f"(c[2]), "+f"(c[3])
        : "r"(a[0]), "r"(a[1]), "r"(a[2]), "r"(a[3]), "r"(b[0]), "r"(b[1]));
}

// ---------------- embedding gathers ----------------
__global__ void embed_enc_k(const int* __restrict__ x, const float* __restrict__ emb,
                            float* __restrict__ Xe) {
    int row = blockIdx.x;
    int t = row >> 6, b = row & 63;
    int tok = x[b * TENC + t];
    const float4* src = (const float4*)(emb + (size_t)tok * DEMB);
    float4* dst = (float4*)(Xe + (size_t)row * DEMB);
    dst[threadIdx.x] = src[threadIdx.x];
}

__global__ void embed_dec_k(const int* __restrict__ labels, const int* __restrict__ bos,
                            const float* __restrict__ emb, float* __restrict__ Xw) {
    int row = blockIdx.x;
    int t = row >> 6, b = row & 63;
    int tok = (t == 0) ? bos[0] : labels[b * TDEC + t - 1];
    const float4* src = (const float4*)(emb + (size_t)tok * DEMB);
    float4* dst = (float4*)(Xw + (size_t)row * DEMB);
    dst[threadIdx.x] = src[threadIdx.x];
}

__global__ void init_all_k(float* __restrict__ h0, float* __restrict__ hd0,
                           const float* __restrict__ dec_init) {
    int b = blockIdx.x, u = threadIdx.x;
    h0[b * H + u] = 0.0f;
    hd0[b * H + u] = dec_init[u];
    if (b == 0 && u == 0) { g_bar_cnt = 0; g_bar_gen = 0; }
}

// ---------------- double-buffered TF32 GEMM ----------------
// C[m,n] = sum_k A[m,k]*W[n*ldw+koff+k] + bias[n]
__global__ __launch_bounds__(256, 2)
void gemm_tf32_k(const float* __restrict__ A, int lda,
                 const float* __restrict__ W, int ldw, int koff,
                 const float* __restrict__ bias,
                 float* __restrict__ C,
                 int M, int N, int K, int trans_out) {
    __shared__ uint32_t As[2][128][20];
    __shared__ uint32_t Bs[2][128][20];

    const int m0 = blockIdx.x * 128, n0 = blockIdx.y * 128;
    const int tid = threadIdx.x, lane = tid & 31, wid = tid >> 5;
    const int wr = wid >> 1, wc = wid & 1;
    const int g = lane >> 2, tg = lane & 3;

    float acc[2][8][4];
#pragma unroll
    for (int ms = 0; ms < 2; ms++)
#pragma unroll
        for (int ns = 0; ns < 8; ns++)
#pragma unroll
            for (int i = 0; i < 4; i++) acc[ms][ns][i] = 0.0f;

    const int lrow = tid >> 1, lcol = (tid & 1) * 8;
    const float* Ap = A + (size_t)(m0 + lrow) * lda + lcol;
    const float* Wp = W + (size_t)(n0 + lrow) * ldw + koff + lcol;
    const bool aok = (m0 + lrow) < M;

    float4 ra0 = make_float4(0.f, 0.f, 0.f, 0.f), ra1 = ra0, rb0, rb1;
    if (aok) { ra0 = *(const float4*)(Ap); ra1 = *(const float4*)(Ap + 4); }
    rb0 = *(const float4*)(Wp); rb1 = *(const float4*)(Wp + 4);

    const int niter = K / 16;
    for (int i = 0; i < niter; i++) {
        const int buf = i & 1;
        cvt_store4(&As[buf][lrow][lcol], ra0);
        cvt_store4(&As[buf][lrow][lcol + 4], ra1);
        cvt_store4(&Bs[buf][lrow][lcol], rb0);
        cvt_store4(&Bs[buf][lrow][lcol + 4], rb1);
        __syncthreads();
        if (i + 1 < niter) {
            int k0 = (i + 1) * 16;
            if (aok) { ra0 = *(const float4*)(Ap + k0); ra1 = *(const float4*)(Ap + k0 + 4); }
            rb0 = *(const float4*)(Wp + k0); rb1 = *(const float4*)(Wp + k0 + 4);
        }
#pragma unroll
        for (int kk = 0; kk < 16; kk += 8) {
            uint32_t a[2][4], b[8][2];
#pragma unroll
            for (int ms = 0; ms < 2; ms++) {
                int r0 = wr * 32 + ms * 16 + g;
                a[ms][0] = As[buf][r0][kk + tg];
                a[ms][1] = As[buf][r0 + 8][kk + tg];
                a[ms][2] = As[buf][r0][kk + tg + 4];
                a[ms][3] = As[buf][r0 + 8][kk + tg + 4];
            }
#pragma unroll
            for (int ns = 0; ns < 8; ns++) {
                int br = wc * 64 + ns * 8 + g;
                b[ns][0] = Bs[buf][br][kk + tg];
                b[ns][1] = Bs[buf][br][kk + tg + 4];
            }
#pragma unroll
            for (int ms = 0; ms < 2; ms++)
#pragma unroll
                for (int ns = 0; ns < 8; ns++)
                    mma_tf32(acc[ms][ns], a[ms], b[ns]);
        }
    }

#pragma unroll
    for (int ms = 0; ms < 2; ms++)
#pragma unroll
        for (int ns = 0; ns < 8; ns++) {
            int row = m0 + wr * 32 + ms * 16 + g;
            int col = n0 + wc * 64 + ns * 8 + 2 * tg;
            float b0 = bias ? bias[col] : 0.0f;
            float b1 = bias ? bias[col + 1] : 0.0f;
#pragma unroll
            for (int h2 = 0; h2 < 2; h2++) {
                int r = row + h2 * 8;
                if (r < M) {
                    size_t idx;
                    if (trans_out) {
                        int bb = r & 63, tt = r >> 6;
                        idx = ((size_t)bb * TDEC + tt) * (size_t)N + col;
                    } else {
                        idx = (size_t)r * (size_t)N + col;
                    }
                    float2 v;
                    v.x = acc[ms][ns][h2 * 2 + 0] + b0;
                    v.y = acc[ms][ns][h2 * 2 + 1] + b1;
                    *(float2*)(C + idx) = v;
                }
            }
        }
}

// ---------------- persistent GRU recurrence ----------------
// 64 CTAs x 256 thr. CTA owns 16 hidden units (48 Whh rows) resident in smem
// as tf32 for all T steps. Grid-wide barrier per step via atomics.
template <bool DEC>
__global__ __launch_bounds__(256, 1)
void gru_persistent_k(float* __restrict__ h0, float* __restrict__ h1,
                      const float* __restrict__ Whh, const float* __restrict__ bhh,
                      const float* __restrict__ gi, const float* __restrict__ ctx,
                      float* __restrict__ st, int T) {
    extern __shared__ uint32_t sm[];
    uint32_t* Wsh = sm;                        // [48][WSH_STRIDE]
    uint32_t* Ash = sm + 48 * WSH_STRIDE;      // [2][64][ASH_STRIDE]
    float* Gsh = (float*)(sm + 48 * WSH_STRIDE); // [2][64][GSH_STRIDE] (union)

    const int u0 = blockIdx.x * 16;
    const int tid = threadIdx.x, lane = tid & 31, wid = tid >> 5;
    const int kg = wid >> 2, mg = (wid >> 1) & 1, ng = wid & 1;
    const int g = lane >> 2, tg = lane & 3;

    // --- load Whh slice into smem (tf32), once ---
    for (int j = 0; j < 48; j++) {
        int grow = (j >> 4) * H + u0 + (j & 15);
        float4 v = *(const float4*)(Whh + (size_t)grow * H + tid * 4);
        cvt_store4(&Wsh[j * WSH_STRIDE + tid * 4], v);
    }

    const int sr = tid >> 2, sc0 = (tid & 3) * 8;

    for (int t = 0; t < T; t++) {
        const float* hin = (t & 1) ? h1 : h0;
        float* hout = (t & 1) ? h0 : h1;
        const float* gi_t = gi + (size_t)t * BATCH * 3 * H;

        float4 p0 = *(const float4*)(hin + sr * H + sc0);
        float4 p1 = *(const float4*)(hin + sr * H + sc0 + 4);

        float acc[2][3][4];
#pragma unroll
        for (int ms = 0; ms < 2; ms++)
#pragma unroll
            for (int ns = 0; ns < 3; ns++)
#pragma unroll
                for (int i = 0; i < 4; i++) acc[ms][ns][i] = 0.0f;

        for (int c = 0; c < 32; c++) {
            uint32_t* Ab = Ash + (c & 1) * 64 * ASH_STRIDE;
            cvt_store4(&Ab[sr * ASH_STRIDE + sc0], p0);
            cvt_store4(&Ab[sr * ASH_STRIDE + sc0 + 4], p1);
            __syncthreads();
            if (c < 31) {
                p0 = *(const float4*)(hin + sr * H + (c + 1) * 32 + sc0);
                p1 = *(const float4*)(hin + sr * H + (c + 1) * 32 + sc0 + 4);
            }
#pragma unroll
            for (int s = 0; s < 2; s++) {
                const int kk = kg * 16 + s * 8;
                const int gk = c * 32 + kk;
                uint32_t a[2][4], b[3][2];
#pragma unroll
                for (int ms = 0; ms < 2; ms++) {
                    int row = mg * 32 + ms * 16 + g;
                    a[ms][0] = Ab[row * ASH_STRIDE + kk + tg];
                    a[ms][1] = Ab[(row + 8) * ASH_STRIDE + kk + tg];
                    a[ms][2] = Ab[row * ASH_STRIDE + kk + tg + 4];
                    a[ms][3] = Ab[(row + 8) * ASH_STRIDE + kk + tg + 4];
                }
#pragma unroll
                for (int ns = 0; ns < 3; ns++) {
                    int br = ng * 24 + ns * 8 + g;
                    b[ns][0] = Wsh[br * WSH_STRIDE + gk + tg];
                    b[ns][1] = Wsh[br * WSH_STRIDE + gk + tg + 4];
                }
#pragma unroll
                for (int ms = 0; ms < 2; ms++)
#pragma unroll
                    for (int ns = 0; ns < 3; ns++)
                        mma_tf32(acc[ms][ns], a[ms], b[ns]);
            }
        }
        __syncthreads();  // all mma done; safe to overwrite Ash with Gsh

#pragma unroll
        for (int ms = 0; ms < 2; ms++)
#pragma unroll
            for (int ns = 0; ns < 3; ns++)
#pragma unroll
                for (int i = 0; i < 4; i++) {
                    int row = mg * 32 + ms * 16 + g + (i >> 1) * 8;
                    int col = ng * 24 + ns * 8 + 2 * tg + (i & 1);
                    Gsh[(kg * 64 + row) * GSH_STRIDE + col] = acc[ms][ns][i];
                }
        __syncthreads();

        // gates: 1024 (b,u) pairs
#pragma unroll
        for (int j = 0; j < 4; j++) {
            int idx = tid + j * 256;
            int b = idx >> 4, ul = idx & 15, u = u0 + ul;
            float aR = Gsh[b * GSH_STRIDE + ul]      + Gsh[(64 + b) * GSH_STRIDE + ul];
            float aZ = Gsh[b * GSH_STRIDE + 16 + ul] + Gsh[(64 + b) * GSH_STRIDE + 16 + ul];
            float aN = Gsh[b * GSH_STRIDE + 32 + ul] + Gsh[(64 + b) * GSH_STRIDE + 32 + ul];
            float gr = gi_t[(size_t)b * 3 * H + u];
            float gz = gi_t[(size_t)b * 3 * H + H + u];
            float gn = gi_t[(size_t)b * 3 * H + 2 * H + u];
            if (DEC) {
                const float* cw = ctx + (size_t)b * 3 * H;
                gr += cw[u]; gz += cw[H + u]; gn += cw[2 * H + u];
            }
            float rr = 1.0f / (1.0f + __expf(-(gr + aR + bhh[u])));
            float zz = 1.0f / (1.0f + __expf(-(gz + aZ + bhh[H + u])));
            float nn = tanhf(gn + rr * (aN + bhh[2 * H + u]));
            float hn = (1.0f - zz) * nn + zz * hin[(size_t)b * H + u];
            hout[(size_t)b * H + u] = hn;
            if (DEC) st[(size_t)t * BATCH * H + (size_t)b * H + u] = hn;
        }

        // grid barrier
        __threadfence();
        __syncthreads();
        if (tid == 0) {
            unsigned old_gen = *(volatile unsigned*)&g_bar_gen;
            unsigned r = atomicAdd(&g_bar_cnt, 1);
            if (r == NCTA - 1) {
                atomicExch(&g_bar_cnt, 0);
                __threadfence();
                atomicAdd(&g_bar_gen, 1);
            } else {
                while (*(volatile unsigned*)&g_bar_gen == old_gen) {}
            }
        }
        __syncthreads();
    }
}

// ---------------- host orchestration ----------------
extern "C" void kernel_launch(void* const* d_in, const int* in_sizes, int n_in,
                              void* d_out, int out_size) {
    const int*   x        = (const int*)d_in[0];
    const int*   labels   = (const int*)d_in[1];
    const int*   bos      = (const int*)d_in[2];
    const float* enc_emb  = (const float*)d_in[3];
    const float* enc_Wih  = (const float*)d_in[4];
    const float* enc_Whh  = (const float*)d_in[5];
    const float* enc_bih  = (const float*)d_in[6];
    const float* enc_bhh  = (const float*)d_in[7];
    const float* dec_emb  = (const float*)d_in[8];
    const float* dec_Wih  = (const float*)d_in[9];
    const float* dec_Whh  = (const float*)d_in[10];
    const float* dec_bih  = (const float*)d_in[11];
    const float* dec_bhh  = (const float*)d_in[12];
    const float* dec_init = (const float*)d_in[13];
    const float* lin_W    = (const float*)d_in[14];
    const float* lin_b    = (const float*)d_in[15];
    float*       out      = (float*)d_out;

    float *Xe, *Xi, *Xw, *Xd, *ctx, *h0, *h1, *hd0, *hd1, *st;
    cudaGetSymbolAddress((void**)&Xe, g_Xe);
    cudaGetSymbolAddress((void**)&Xi, g_Xi);
    cudaGetSymbolAddress((void**)&Xw, g_Xw);
    cudaGetSymbolAddress((void**)&Xd, g_Xd);
    cudaGetSymbolAddress((void**)&ctx, g_ctx);
    cudaGetSymbolAddress((void**)&h0, g_h0);
    cudaGetSymbolAddress((void**)&h1, g_h1);
    cudaGetSymbolAddress((void**)&hd0, g_hd0);
    cudaGetSymbolAddress((void**)&hd1, g_hd1);
    cudaGetSymbolAddress((void**)&st, g_st);

    cudaFuncSetAttribute(gru_persistent_k<false>,
                         cudaFuncAttributeMaxDynamicSharedMemorySize, SMEM_BYTES);
    cudaFuncSetAttribute(gru_persistent_k<true>,
                         cudaFuncAttributeMaxDynamicSharedMemorySize, SMEM_BYTES);

    // ---- encoder ----
    embed_enc_k<<<TENC * BATCH, 128>>>(x, enc_emb, Xe);
    init_all_k<<<BATCH, H>>>(h0, hd0, dec_init);
    gemm_tf32_k<<<dim3(64, 24), 256>>>(Xe, DEMB, enc_Wih, DEMB, 0, enc_bih, Xi,
                                       TENC * BATCH, 3 * H, DEMB, 0);
    gru_persistent_k<false><<<NCTA, 256, SMEM_BYTES>>>(h0, h1, enc_Whh, enc_bhh,
                                                       Xi, nullptr, nullptr, TENC);
    float* efin = h0;  // TENC even -> final state in h0

    // ---- decoder precompute ----
    embed_dec_k<<<TDEC * BATCH, 128>>>(labels, bos, dec_emb, Xw);
    gemm_tf32_k<<<dim3(32, 24), 256>>>(Xw, DEMB, dec_Wih, DEMB + H, 0, dec_bih, Xd,
                                       TDEC * BATCH, 3 * H, DEMB, 0);
    gemm_tf32_k<<<dim3(1, 24), 256>>>(efin, H, dec_Wih, DEMB + H, DEMB, nullptr, ctx,
                                      BATCH, 3 * H, H, 0);
    gru_persistent_k<true><<<NCTA, 256, SMEM_BYTES>>>(hd0, hd1, dec_Whh, dec_bhh,
                                                      Xd, ctx, st, TDEC);

    // ---- logits ----
    gemm_tf32_k<<<dim3(32, 250), 256>>>(st, H, lin_W, H, 0, lin_b, out,
                                        TDEC * BATCH, VOCAB, H, 1);
}

// round 4
// speedup vs baseline: 2.7436x; 1.4994x over previous
#include <cuda_runtime.h>
#include <cuda_fp16.h>
#include <cstdint>
#include <math.h>

#define H     1024
#define BATCH 64
#define TENC  128
#define TDEC  64
#define VOCAB 32000
#define DEMB  512
#define NCTA  64

// ---------------- persistent-GRU smem layout (half2 words for W/A, fp32 for G) ----------
#define WSH_STRIDE 516            // half2 words per Whh row (512 + 4 pad)
#define ASH_STRIDE 20             // half2 words per h-tile row (16 + 4 pad)
#define GSH_STRIDE 52
#define GRU_SMEM_BYTES ((48 * WSH_STRIDE + 2 * 64 * GSH_STRIDE) * 4)

// ---------------- fp16 GEMM smem layout ----------------
#define GRS_B 80                  // bytes per smem row (32 halves = 64B + 16B pad)
#define GSTAGE (128 * GRS_B * 2)  // A tile + B tile = 20480 B
#define GEMM_SMEM_BYTES (3 * GSTAGE)

// ---------------- scratch ----------------
__device__ __half g_Xe[(size_t)TENC * BATCH * DEMB];
__device__ float  g_Xi[(size_t)TENC * BATCH * 3 * H];
__device__ __half g_Xw[(size_t)TDEC * BATCH * DEMB];
__device__ float  g_Xd[(size_t)TDEC * BATCH * 3 * H];
__device__ float  g_ctx[(size_t)BATCH * 3 * H];
__device__ float  g_h0[(size_t)BATCH * H];
__device__ float  g_h1[(size_t)BATCH * H];
__device__ float  g_hd0[(size_t)BATCH * H];
__device__ float  g_hd1[(size_t)BATCH * H];
__device__ __half g_st[(size_t)TDEC * BATCH * H];
__device__ __half g_We[(size_t)3 * H * DEMB];
__device__ __half g_Wd[(size_t)3 * H * DEMB];
__device__ __half g_Wl[(size_t)VOCAB * H];
__device__ unsigned g_bar_cnt;
__device__ unsigned g_bar_gen;

// ---------------- helpers ----------------
__device__ __forceinline__ uint32_t pack2(float x, float y) {
    __half2 h = __floats2half2_rn(x, y);
    return *(uint32_t*)&h;
}
__device__ __forceinline__ uint32_t f2tf32(float f) {
    uint32_t r;
    asm("cvt.rna.tf32.f32 %0, %1;" : "=r"(r) : "f"(f));
    return r;
}
__device__ __forceinline__ void cvt_store4(uint32_t* dst, float4 v) {
    dst[0] = f2tf32(v.x); dst[1] = f2tf32(v.y);
    dst[2] = f2tf32(v.z); dst[3] = f2tf32(v.w);
}
__device__ __forceinline__ void mma_f16(float* c, const uint32_t* a, const uint32_t* b) {
    asm volatile(
        "mma.sync.aligned.m16n8k16.row.col.f32.f16.f16.f32 "
        "{%0,%1,%2,%3}, {%4,%5,%6,%7}, {%8,%9}, {%0,%1,%2,%3};\n"
        : "+f"(c[0]), "+f"(c[1]), "+f"(c[2]), "+f"(c[3])
        : "r"(a[0]), "r"(a[1]), "r"(a[2]), "r"(a[3]), "r"(b[0]), "r"(b[1]));
}
__device__ __forceinline__ void mma_tf32(float* c, const uint32_t* a, const uint32_t* b) {
    asm volatile(
        "mma.sync.aligned.m16n8k8.row.col.f32.tf32.tf32.f32 "
        "{%0,%1,%2,%3}, {%4,%5,%6,%7}, {%8,%9}, {%0,%1,%2,%3};\n"
        : "+f"(c[0]), "+f"(c[1]), "+f"(c[2]), "+f"(c[3])
        : "r"(a[0]), "r"(a[1]), "r"(a[2]), "r"(a[3]), "r"(b[0]), "r"(b[1]));
}
__device__ __forceinline__ uint32_t smem_u32(const void* p) {
    uint32_t a;
    asm("{ .reg .u64 t; cvta.to.shared.u64 t, %1; cvt.u32.u64 %0, t; }" : "=r"(a) : "l"(p));
    return a;
}
__device__ __forceinline__ void cp16(uint32_t dst, const void* src) {
    asm volatile("cp.async.cg.shared.global [%0], [%1], 16;\n" :: "r"(dst), "l"(src) : "memory");
}

// ---------------- weight fp16 conversion ----------------
__global__ void conv_k(const float* __restrict__ src, __half* __restrict__ dst, int n8) {
    int i = blockIdx.x * 256 + threadIdx.x;
    if (i < n8) {
        float4 a = ((const float4*)src)[2 * i];
        float4 b = ((const float4*)src)[2 * i + 1];
        uint4 u;
        u.x = pack2(a.x, a.y); u.y = pack2(a.z, a.w);
        u.z = pack2(b.x, b.y); u.w = pack2(b.z, b.w);
        ((uint4*)dst)[i] = u;
    }
}
__global__ void conv_slice_k(const float* __restrict__ src, __half* __restrict__ dst) {
    int r = blockIdx.x;  // 3072 rows; take first 512 of 1536 cols
    float4 v = ((const float4*)(src + (size_t)r * (DEMB + H)))[threadIdx.x];
    uint2 u; u.x = pack2(v.x, v.y); u.y = pack2(v.z, v.w);
    ((uint2*)(dst + (size_t)r * DEMB))[threadIdx.x] = u;
}

// ---------------- embedding gathers -> fp16 ----------------
__global__ void embed_enc_k(const int* __restrict__ x, const float* __restrict__ emb,
                            __half* __restrict__ Xe) {
    int row = blockIdx.x;
    int t = row >> 6, b = row & 63;
    int tok = x[b * TENC + t];
    float4 v = ((const float4*)(emb + (size_t)tok * DEMB))[threadIdx.x];
    uint2 u; u.x = pack2(v.x, v.y); u.y = pack2(v.z, v.w);
    ((uint2*)(Xe + (size_t)row * DEMB))[threadIdx.x] = u;
}
__global__ void embed_dec_k(const int* __restrict__ labels, const int* __restrict__ bos,
                            const float* __restrict__ emb, __half* __restrict__ Xw) {
    int row = blockIdx.x;
    int t = row >> 6, b = row & 63;
    int tok = (t == 0) ? bos[0] : labels[b * TDEC + t - 1];
    float4 v = ((const float4*)(emb + (size_t)tok * DEMB))[threadIdx.x];
    uint2 u; u.x = pack2(v.x, v.y); u.y = pack2(v.z, v.w);
    ((uint2*)(Xw + (size_t)row * DEMB))[threadIdx.x] = u;
}

__global__ void init_all_k(float* __restrict__ h0, float* __restrict__ hd0,
                           const float* __restrict__ dec_init) {
    int b = blockIdx.x, u = threadIdx.x;
    h0[b * H + u] = 0.0f;
    hd0[b * H + u] = dec_init[u];
    if (b == 0 && u == 0) { g_bar_cnt = 0; g_bar_gen = 0; }
}

// ---------------- fp16 GEMM: C(MxN fp32) = A(MxK h) @ B(NxK h)^T + bias ----------------
// BM=128, BN=128, BK=32. 3-stage cp.async pipeline. 8 warps (4x2), warp tile 32x64.
__global__ __launch_bounds__(256, 2)
void gemm_f16_k(const __half* __restrict__ A, const __half* __restrict__ B,
                const float* __restrict__ bias, float* __restrict__ C,
                int N, int K, int trans_out) {
    extern __shared__ char smc[];
    const uint32_t sb = smem_u32(smc);
    const int m0 = blockIdx.x * 128, n0 = blockIdx.y * 128;
    const int tid = threadIdx.x, lane = tid & 31, wid = tid >> 5;
    const int wr = wid >> 1, wc = wid & 1;
    const int g = lane >> 2, tg = lane & 3;

    float acc[2][8][4];
#pragma unroll
    for (int ms = 0; ms < 2; ms++)
#pragma unroll
        for (int ns = 0; ns < 8; ns++)
#pragma unroll
            for (int i = 0; i < 4; i++) acc[ms][ns][i] = 0.0f;

    const __half* Ab = A + (size_t)m0 * K;
    const __half* Bb = B + (size_t)n0 * K;

    auto load_stage = [&](int s, int k0) {
        uint32_t sbase = sb + s * GSTAGE;
#pragma unroll
        for (int i = 0; i < 2; i++) {
            int idx = tid + i * 256;
            int row = idx >> 2, c = idx & 3;
            cp16(sbase + row * GRS_B + c * 16, Ab + (size_t)row * K + k0 + c * 8);
        }
#pragma unroll
        for (int i = 0; i < 2; i++) {
            int idx = tid + i * 256;
            int row = idx >> 2, c = idx & 3;
            cp16(sbase + 128 * GRS_B + row * GRS_B + c * 16, Bb + (size_t)row * K + k0 + c * 8);
        }
        asm volatile("cp.async.commit_group;\n" ::: "memory");
    };

    const int NT = K >> 5;
    load_stage(0, 0);
    load_stage(1, 32);

    for (int it = 0; it < NT; ++it) {
        const int s = it % 3;
        if (it == NT - 1) asm volatile("cp.async.wait_group 0;\n" ::: "memory");
        else              asm volatile("cp.async.wait_group 1;\n" ::: "memory");
        __syncthreads();
        if (it + 2 < NT) load_stage((it + 2) % 3, (it + 2) * 32);

        const uint32_t* As = (const uint32_t*)(smc + s * GSTAGE);
        const uint32_t* Bs = (const uint32_t*)(smc + s * GSTAGE + 128 * GRS_B);
#pragma unroll
        for (int kk = 0; kk < 2; kk++) {
            const int c0 = kk * 8;
            uint32_t a[2][4], b[8][2];
#pragma unroll
            for (int ms = 0; ms < 2; ms++) {
                int r0 = wr * 32 + ms * 16 + g;
                a[ms][0] = As[r0 * 20 + c0 + tg];
                a[ms][1] = As[(r0 + 8) * 20 + c0 + tg];
                a[ms][2] = As[r0 * 20 + c0 + tg + 4];
                a[ms][3] = As[(r0 + 8) * 20 + c0 + tg + 4];
            }
#pragma unroll
            for (int ns = 0; ns < 8; ns++) {
                int br = wc * 64 + ns * 8 + g;
                b[ns][0] = Bs[br * 20 + c0 + tg];
                b[ns][1] = Bs[br * 20 + c0 + tg + 4];
            }
#pragma unroll
            for (int ms = 0; ms < 2; ms++)
#pragma unroll
                for (int ns = 0; ns < 8; ns++)
                    mma_f16(acc[ms][ns], a[ms], b[ns]);
        }
        __syncthreads();
    }

#pragma unroll
    for (int ms = 0; ms < 2; ms++)
#pragma unroll
        for (int ns = 0; ns < 8; ns++) {
            int row = m0 + wr * 32 + ms * 16 + g;
            int col = n0 + wc * 64 + ns * 8 + 2 * tg;
            float b0 = bias[col], b1 = bias[col + 1];
#pragma unroll
            for (int h2 = 0; h2 < 2; h2++) {
                int r = row + h2 * 8;
                size_t idx;
                if (trans_out) {
                    int bb = r & 63, tt = r >> 6;
                    idx = ((size_t)bb * TDEC + tt) * (size_t)N + col;
                } else {
                    idx = (size_t)r * (size_t)N + col;
                }
                float2 v;
                v.x = acc[ms][ns][h2 * 2 + 0] + b0;
                v.y = acc[ms][ns][h2 * 2 + 1] + b1;
                *(float2*)(C + idx) = v;
            }
        }
}

// ---------------- small tf32 GEMM (ctx only: 64 x 3072 x 1024) ----------------
__global__ __launch_bounds__(256, 2)
void gemm_tf32_k(const float* __restrict__ A, int lda,
                 const float* __restrict__ W, int ldw, int koff,
                 float* __restrict__ C, int M, int N, int K) {
    __shared__ uint32_t As[128][20];
    __shared__ uint32_t Bs[128][20];
    const int m0 = blockIdx.x * 128, n0 = blockIdx.y * 128;
    const int tid = threadIdx.x, lane = tid & 31, wid = tid >> 5;
    const int wr = wid >> 1, wc = wid & 1;
    const int g = lane >> 2, tg = lane & 3;
    float acc[2][8][4];
#pragma unroll
    for (int ms = 0; ms < 2; ms++)
#pragma unroll
        for (int ns = 0; ns < 8; ns++)
#pragma unroll
            for (int i = 0; i < 4; i++) acc[ms][ns][i] = 0.0f;
    const int lrow = tid >> 1, lcol = (tid & 1) * 8;
    const float* Ap = A + (size_t)(m0 + lrow) * lda + lcol;
    const float* Wp = W + (size_t)(n0 + lrow) * ldw + koff + lcol;
    const bool aok = (m0 + lrow) < M;
    for (int k0 = 0; k0 < K; k0 += 16) {
        if (aok) {
            cvt_store4(&As[lrow][lcol], *(const float4*)(Ap + k0));
            cvt_store4(&As[lrow][lcol + 4], *(const float4*)(Ap + k0 + 4));
        } else {
#pragma unroll
            for (int i = 0; i < 8; i++) As[lrow][lcol + i] = 0u;
        }
        cvt_store4(&Bs[lrow][lcol], *(const float4*)(Wp + k0));
        cvt_store4(&Bs[lrow][lcol + 4], *(const float4*)(Wp + k0 + 4));
        __syncthreads();
#pragma unroll
        for (int kk = 0; kk < 16; kk += 8) {
            uint32_t a[2][4], b[8][2];
#pragma unroll
            for (int ms = 0; ms < 2; ms++) {
                int r0 = wr * 32 + ms * 16 + g;
                a[ms][0] = As[r0][kk + tg]; a[ms][1] = As[r0 + 8][kk + tg];
                a[ms][2] = As[r0][kk + tg + 4]; a[ms][3] = As[r0 + 8][kk + tg + 4];
            }
#pragma unroll
            for (int ns = 0; ns < 8; ns++) {
                int br = wc * 64 + ns * 8 + g;
                b[ns][0] = Bs[br][kk + tg]; b[ns][1] = Bs[br][kk + tg + 4];
            }
#pragma unroll
            for (int ms = 0; ms < 2; ms++)
#pragma unroll
                for (int ns = 0; ns < 8; ns++) mma_tf32(acc[ms][ns], a[ms], b[ns]);
        }
        __syncthreads();
    }
#pragma unroll
    for (int ms = 0; ms < 2; ms++)
#pragma unroll
        for (int ns = 0; ns < 8; ns++) {
            int row = m0 + wr * 32 + ms * 16 + g;
            int col = n0 + wc * 64 + ns * 8 + 2 * tg;
#pragma unroll
            for (int h2 = 0; h2 < 2; h2++) {
                int r = row + h2 * 8;
                if (r < M) {
                    size_t idx = (size_t)r * (size_t)N + col;
                    float2 v;
                    v.x = acc[ms][ns][h2 * 2 + 0];
                    v.y = acc[ms][ns][h2 * 2 + 1];
                    *(float2*)(C + idx) = v;
                }
            }
        }
}

// ---------------- persistent GRU recurrence (fp16 mma) ----------------
// 64 CTAs x 256 thr. CTA owns 16 hidden units (48 Whh rows) resident in smem as half2.
template <bool DEC>
__global__ __launch_bounds__(256, 1)
void gru_persistent_k(float* __restrict__ h0, float* __restrict__ h1,
                      const float* __restrict__ Whh, const float* __restrict__ bhh,
                      const float* __restrict__ gi, const float* __restrict__ ctx,
                      __half* __restrict__ st, int T) {
    extern __shared__ uint32_t sm[];
    uint32_t* Wsh = sm;                             // [48][WSH_STRIDE] half2 words
    uint32_t* Ash = sm + 48 * WSH_STRIDE;           // [2][64][ASH_STRIDE] half2 words
    float* Gsh = (float*)(sm + 48 * WSH_STRIDE);    // union: [2][64][GSH_STRIDE] fp32

    const int u0 = blockIdx.x * 16;
    const int tid = threadIdx.x, lane = tid & 31, wid = tid >> 5;
    const int kg = wid >> 2, mg = (wid >> 1) & 1, ng = wid & 1;
    const int g = lane >> 2, tg = lane & 3;

    // load Whh slice, convert to half2, once
    for (int j = 0; j < 48; j++) {
        int grow = (j >> 4) * H + u0 + (j & 15);
        float4 v = *(const float4*)(Whh + (size_t)grow * H + tid * 4);
        Wsh[j * WSH_STRIDE + tid * 2]     = pack2(v.x, v.y);
        Wsh[j * WSH_STRIDE + tid * 2 + 1] = pack2(v.z, v.w);
    }
    const int sr = tid >> 2, sc0 = (tid & 3) * 4;   // half2 col base (4 half2 = 8 floats)

    for (int t = 0; t < T; t++) {
        const float* hin = (t & 1) ? h1 : h0;
        float* hout = (t & 1) ? h0 : h1;
        const float* gi_t = gi + (size_t)t * BATCH * 3 * H;

        float4 p0 = *(const float4*)(hin + sr * H + (tid & 3) * 8);
        float4 p1 = *(const float4*)(hin + sr * H + (tid & 3) * 8 + 4);

        float acc[2][3][4];
#pragma unroll
        for (int ms = 0; ms < 2; ms++)
#pragma unroll
            for (int ns = 0; ns < 3; ns++)
#pragma unroll
                for (int i = 0; i < 4; i++) acc[ms][ns][i] = 0.0f;

        for (int c = 0; c < 32; c++) {           // k32 chunks
            uint32_t* Ab = Ash + (c & 1) * 64 * ASH_STRIDE;
            Ab[sr * ASH_STRIDE + sc0]     = pack2(p0.x, p0.y);
            Ab[sr * ASH_STRIDE + sc0 + 1] = pack2(p0.z, p0.w);
            Ab[sr * ASH_STRIDE + sc0 + 2] = pack2(p1.x, p1.y);
            Ab[sr * ASH_STRIDE + sc0 + 3] = pack2(p1.z, p1.w);
            __syncthreads();
            if (c < 31) {
                p0 = *(const float4*)(hin + sr * H + (c + 1) * 32 + (tid & 3) * 8);
                p1 = *(const float4*)(hin + sr * H + (c + 1) * 32 + (tid & 3) * 8 + 4);
            }
            // warp's k16 chunk: half2 col base kg*8
            {
                const int c0 = kg * 8;
                const int wc0 = c * 16 + kg * 8;
                uint32_t a[2][4], b[3][2];
#pragma unroll
                for (int ms = 0; ms < 2; ms++) {
                    int row = mg * 32 + ms * 16 + g;
                    a[ms][0] = Ab[row * ASH_STRIDE + c0 + tg];
                    a[ms][1] = Ab[(row + 8) * ASH_STRIDE + c0 + tg];
                    a[ms][2] = Ab[row * ASH_STRIDE + c0 + tg + 4];
                    a[ms][3] = Ab[(row + 8) * ASH_STRIDE + c0 + tg + 4];
                }
#pragma unroll
                for (int ns = 0; ns < 3; ns++) {
                    int br = ng * 24 + ns * 8 + g;
                    b[ns][0] = Wsh[br * WSH_STRIDE + wc0 + tg];
                    b[ns][1] = Wsh[br * WSH_STRIDE + wc0 + tg + 4];
                }
#pragma unroll
                for (int ms = 0; ms < 2; ms++)
#pragma unroll
                    for (int ns = 0; ns < 3; ns++) mma_f16(acc[ms][ns], a[ms], b[ns]);
            }
        }
        __syncthreads();

#pragma unroll
        for (int ms = 0; ms < 2; ms++)
#pragma unroll
            for (int ns = 0; ns < 3; ns++)
#pragma unroll
                for (int i = 0; i < 4; i++) {
                    int row = mg * 32 + ms * 16 + g + (i >> 1) * 8;
                    int col = ng * 24 + ns * 8 + 2 * tg + (i & 1);
                    Gsh[(kg * 64 + row) * GSH_STRIDE + col] = acc[ms][ns][i];
                }
        __syncthreads();

#pragma unroll
        for (int j = 0; j < 4; j++) {
            int idx = tid + j * 256;
            int b = idx >> 4, ul = idx & 15, u = u0 + ul;
            float aR = Gsh[b * GSH_STRIDE + ul]      + Gsh[(64 + b) * GSH_STRIDE + ul];
            float aZ = Gsh[b * GSH_STRIDE + 16 + ul] + Gsh[(64 + b) * GSH_STRIDE + 16 + ul];
            float aN = Gsh[b * GSH_STRIDE + 32 + ul] + Gsh[(64 + b) * GSH_STRIDE + 32 + ul];
            float gr = gi_t[(size_t)b * 3 * H + u];
            float gz = gi_t[(size_t)b * 3 * H + H + u];
            float gn = gi_t[(size_t)b * 3 * H + 2 * H + u];
            if (DEC) {
                const float* cw = ctx + (size_t)b * 3 * H;
                gr += cw[u]; gz += cw[H + u]; gn += cw[2 * H + u];
            }
            float rr = 1.0f / (1.0f + __expf(-(gr + aR + bhh[u])));
            float zz = 1.0f / (1.0f + __expf(-(gz + aZ + bhh[H + u])));
            float nn = tanhf(gn + rr * (aN + bhh[2 * H + u]));
            float hn = (1.0f - zz) * nn + zz * hin[(size_t)b * H + u];
            hout[(size_t)b * H + u] = hn;
            if (DEC) st[(size_t)t * BATCH * H + (size_t)b * H + u] = __float2half_rn(hn);
        }

        __threadfence();
        __syncthreads();
        if (tid == 0) {
            unsigned old_gen = *(volatile unsigned*)&g_bar_gen;
            unsigned r = atomicAdd(&g_bar_cnt, 1);
            if (r == NCTA - 1) {
                atomicExch(&g_bar_cnt, 0);
                __threadfence();
                atomicAdd(&g_bar_gen, 1);
            } else {
                while (*(volatile unsigned*)&g_bar_gen == old_gen) {}
            }
        }
        __syncthreads();
    }
}

// ---------------- host orchestration ----------------
extern "C" void kernel_launch(void* const* d_in, const int* in_sizes, int n_in,
                              void* d_out, int out_size) {
    const int*   x        = (const int*)d_in[0];
    const int*   labels   = (const int*)d_in[1];
    const int*   bos      = (const int*)d_in[2];
    const float* enc_emb  = (const float*)d_in[3];
    const float* enc_Wih  = (const float*)d_in[4];
    const float* enc_Whh  = (const float*)d_in[5];
    const float* enc_bih  = (const float*)d_in[6];
    const float* enc_bhh  = (const float*)d_in[7];
    const float* dec_emb  = (const float*)d_in[8];
    const float* dec_Wih  = (const float*)d_in[9];
    const float* dec_Whh  = (const float*)d_in[10];
    const float* dec_bih  = (const float*)d_in[11];
    const float* dec_bhh  = (const float*)d_in[12];
    const float* dec_init = (const float*)d_in[13];
    const float* lin_W    = (const float*)d_in[14];
    const float* lin_b    = (const float*)d_in[15];
    float*       out      = (float*)d_out;

    __half *Xe, *Xw, *st, *We, *Wd, *Wl;
    float *Xi, *Xd, *ctx, *h0, *h1, *hd0, *hd1;
    cudaGetSymbolAddress((void**)&Xe, g_Xe);
    cudaGetSymbolAddress((void**)&Xi, g_Xi);
    cudaGetSymbolAddress((void**)&Xw, g_Xw);
    cudaGetSymbolAddress((void**)&Xd, g_Xd);
    cudaGetSymbolAddress((void**)&ctx, g_ctx);
    cudaGetSymbolAddress((void**)&h0, g_h0);
    cudaGetSymbolAddress((void**)&h1, g_h1);
    cudaGetSymbolAddress((void**)&hd0, g_hd0);
    cudaGetSymbolAddress((void**)&hd1, g_hd1);
    cudaGetSymbolAddress((void**)&st, g_st);
    cudaGetSymbolAddress((void**)&We, g_We);
    cudaGetSymbolAddress((void**)&Wd, g_Wd);
    cudaGetSymbolAddress((void**)&Wl, g_Wl);

    cudaFuncSetAttribute(gru_persistent_k<false>,
                         cudaFuncAttributeMaxDynamicSharedMemorySize, GRU_SMEM_BYTES);
    cudaFuncSetAttribute(gru_persistent_k<true>,
                         cudaFuncAttributeMaxDynamicSharedMemorySize, GRU_SMEM_BYTES);
    cudaFuncSetAttribute(gemm_f16_k,
                         cudaFuncAttributeMaxDynamicSharedMemorySize, GEMM_SMEM_BYTES);

    // ---- fp16 weight conversion ----
    conv_k<<<(3 * H * DEMB / 8 + 255) / 256, 256>>>(enc_Wih, We, 3 * H * DEMB / 8);
    conv_slice_k<<<3 * H, 128>>>(dec_Wih, Wd);
    conv_k<<<((size_t)VOCAB * H / 8 + 255) / 256, 256>>>(lin_W, Wl, VOCAB * H / 8);

    // ---- encoder ----
    embed_enc_k<<<TENC * BATCH, 128>>>(x, enc_emb, Xe);
    init_all_k<<<BATCH, H>>>(h0, hd0, dec_init);
    gemm_f16_k<<<dim3(TENC * BATCH / 128, 3 * H / 128), 256, GEMM_SMEM_BYTES>>>(
        Xe, We, enc_bih, Xi, 3 * H, DEMB, 0);
    gru_persistent_k<false><<<NCTA, 256, GRU_SMEM_BYTES>>>(h0, h1, enc_Whh, enc_bhh,
                                                           Xi, nullptr, nullptr, TENC);
    float* efin = h0;  // TENC even -> final state in h0

    // ---- decoder precompute ----
    embed_dec_k<<<TDEC * BATCH, 128>>>(labels, bos, dec_emb, Xw);
    gemm_f16_k<<<dim3(TDEC * BATCH / 128, 3 * H / 128), 256, GEMM_SMEM_BYTES>>>(
        Xw, Wd, dec_bih, Xd, 3 * H, DEMB, 0);
    gemm_tf32_k<<<dim3(1, 24), 256>>>(efin, H, dec_Wih, DEMB + H, DEMB, ctx,
                                      BATCH, 3 * H, H);
    gru_persistent_k<true><<<NCTA, 256, GRU_SMEM_BYTES>>>(hd0, hd1, dec_Whh, dec_bhh,
                                                          Xd, ctx, st, TDEC);

    // ---- logits ----
    gemm_f16_k<<<dim3(TDEC * BATCH / 128, VOCAB / 128), 256, GEMM_SMEM_BYTES>>>(
        st, Wl, lin_b, out, VOCAB, H, 1);
}

// round 5
// speedup vs baseline: 2.8898x; 1.0533x over previous
#include <cuda_runtime.h>
#include <cuda_fp16.h>
#include <cstdint>
#include <math.h>

#define H     1024
#define BATCH 64
#define TENC  128
#define TDEC  64
#define VOCAB 32000
#define DEMB  512
#define NCTA  64

// ---------------- persistent-GRU smem layout (half2 words for W/A, fp32 for G) ----------
#define WSH_STRIDE 516
#define ASH_STRIDE 20
#define GSH_STRIDE 52
#define GRU_SMEM_BYTES ((48 * WSH_STRIDE + 2 * 64 * GSH_STRIDE) * 4)

// ---------------- fp16 GEMM smem layout: BK=64, swizzled 128B rows ----------------
#define GSTG 32768                 // A 16KB + B 16KB per stage
#define GEMM_SMEM_BYTES (3 * GSTG) // 96KB, 2 CTAs/SM

// ---------------- scratch ----------------
__device__ __half g_Xe[(size_t)TENC * BATCH * DEMB];
__device__ float  g_Xi[(size_t)TENC * BATCH * 3 * H];
__device__ __half g_Xw[(size_t)TDEC * BATCH * DEMB];
__device__ float  g_Xd[(size_t)TDEC * BATCH * 3 * H];
__device__ float  g_ctx[(size_t)BATCH * 3 * H];
__device__ float  g_h0[(size_t)BATCH * H];
__device__ float  g_h1[(size_t)BATCH * H];
__device__ float  g_hd0[(size_t)BATCH * H];
__device__ float  g_hd1[(size_t)BATCH * H];
__device__ __half g_st[(size_t)TDEC * BATCH * H];
__device__ __half g_We[(size_t)3 * H * DEMB];
__device__ __half g_Wd[(size_t)3 * H * DEMB];
__device__ __half g_Wl[(size_t)VOCAB * H];
__device__ unsigned g_bar_cnt;
__device__ unsigned g_bar_gen;

// ---------------- helpers ----------------
__device__ __forceinline__ uint32_t pack2(float x, float y) {
    __half2 h = __floats2half2_rn(x, y);
    return *(uint32_t*)&h;
}
__device__ __forceinline__ uint32_t f2tf32(float f) {
    uint32_t r;
    asm("cvt.rna.tf32.f32 %0, %1;" : "=r"(r) : "f"(f));
    return r;
}
__device__ __forceinline__ void cvt_store4(uint32_t* dst, float4 v) {
    dst[0] = f2tf32(v.x); dst[1] = f2tf32(v.y);
    dst[2] = f2tf32(v.z); dst[3] = f2tf32(v.w);
}
__device__ __forceinline__ void mma_f16(float* c, const uint32_t* a, const uint32_t* b) {
    asm volatile(
        "mma.sync.aligned.m16n8k16.row.col.f32.f16.f16.f32 "
        "{%0,%1,%2,%3}, {%4,%5,%6,%7}, {%8,%9}, {%0,%1,%2,%3};\n"
        : "+f"(c[0]), "+f"(c[1]), "+f"(c[2]), "+f"(c[3])
        : "r"(a[0]), "r"(a[1]), "r"(a[2]), "r"(a[3]), "r"(b[0]), "r"(b[1]));
}
__device__ __forceinline__ void mma_tf32(float* c, const uint32_t* a, const uint32_t* b) {
    asm volatile(
        "mma.sync.aligned.m16n8k8.row.col.f32.tf32.tf32.f32 "
        "{%0,%1,%2,%3}, {%4,%5,%6,%7}, {%8,%9}, {%0,%1,%2,%3};\n"
        : "+f"(c[0]), "+f"(c[1]), "+f"(c[2]), "+f"(c[3])
        : "r"(a[0]), "r"(a[1]), "r"(a[2]), "r"(a[3]), "r"(b[0]), "r"(b[1]));
}
__device__ __forceinline__ uint32_t smem_u32(const void* p) {
    uint32_t a;
    asm("{ .reg .u64 t; cvta.to.shared.u64 t, %1; cvt.u32.u64 %0, t; }" : "=r"(a) : "l"(p));
    return a;
}
__device__ __forceinline__ uint32_t swz128(uint32_t o) { return o ^ ((o >> 3) & 0x70); }
__device__ __forceinline__ void cp16(uint32_t dst, const void* src) {
    asm volatile("cp.async.cg.shared.global [%0], [%1], 16;\n" :: "r"(dst), "l"(src) : "memory");
}
#define LDSM4(r0, r1, r2, r3, addr) \
    asm volatile("ldmatrix.sync.aligned.m8n8.x4.shared.b16 {%0,%1,%2,%3}, [%4];" \
                 : "=r"(r0), "=r"(r1), "=r"(r2), "=r"(r3) : "r"(addr))

// ---------------- weight fp16 conversion ----------------
__global__ void conv_k(const float* __restrict__ src, __half* __restrict__ dst, int n8) {
    int i = blockIdx.x * 256 + threadIdx.x;
    if (i < n8) {
        float4 a = ((const float4*)src)[2 * i];
        float4 b = ((const float4*)src)[2 * i + 1];
        uint4 u;
        u.x = pack2(a.x, a.y); u.y = pack2(a.z, a.w);
        u.z = pack2(b.x, b.y); u.w = pack2(b.z, b.w);
        ((uint4*)dst)[i] = u;
    }
}
__global__ void conv_slice_k(const float* __restrict__ src, __half* __restrict__ dst) {
    int r = blockIdx.x;
    float4 v = ((const float4*)(src + (size_t)r * (DEMB + H)))[threadIdx.x];
    uint2 u; u.x = pack2(v.x, v.y); u.y = pack2(v.z, v.w);
    ((uint2*)(dst + (size_t)r * DEMB))[threadIdx.x] = u;
}

// ---------------- embedding gathers -> fp16 ----------------
__global__ void embed_enc_k(const int* __restrict__ x, const float* __restrict__ emb,
                            __half* __restrict__ Xe) {
    int row = blockIdx.x;
    int t = row >> 6, b = row & 63;
    int tok = x[b * TENC + t];
    float4 v = ((const float4*)(emb + (size_t)tok * DEMB))[threadIdx.x];
    uint2 u; u.x = pack2(v.x, v.y); u.y = pack2(v.z, v.w);
    ((uint2*)(Xe + (size_t)row * DEMB))[threadIdx.x] = u;
}
__global__ void embed_dec_k(const int* __restrict__ labels, const int* __restrict__ bos,
                            const float* __restrict__ emb, __half* __restrict__ Xw) {
    int row = blockIdx.x;
    int t = row >> 6, b = row & 63;
    int tok = (t == 0) ? bos[0] : labels[b * TDEC + t - 1];
    float4 v = ((const float4*)(emb + (size_t)tok * DEMB))[threadIdx.x];
    uint2 u; u.x = pack2(v.x, v.y); u.y = pack2(v.z, v.w);
    ((uint2*)(Xw + (size_t)row * DEMB))[threadIdx.x] = u;
}

__global__ void init_all_k(float* __restrict__ h0, float* __restrict__ hd0,
                           const float* __restrict__ dec_init) {
    int b = blockIdx.x, u = threadIdx.x;
    h0[b * H + u] = 0.0f;
    hd0[b * H + u] = dec_init[u];
    if (b == 0 && u == 0) { g_bar_cnt = 0; g_bar_gen = 0; }
}

// ---------------- fp16 GEMM: C(MxN fp32) = A(MxK h) @ B(NxK h)^T + bias ----------------
// BM=128, BN=128, BK=64. 3-stage cp.async. ldmatrix operands, XOR-swizzled smem.
__global__ __launch_bounds__(256, 2)
void gemm_f16_k(const __half* __restrict__ A, const __half* __restrict__ B,
                const float* __restrict__ bias, float* __restrict__ C,
                int N, int K, int trans_out) {
    extern __shared__ char smc[];
    const uint32_t sb = smem_u32(smc);
    const int m0 = blockIdx.x * 128, n0 = blockIdx.y * 128;
    const int tid = threadIdx.x, lane = tid & 31, wid = tid >> 5;
    const int wr = wid >> 1, wc = wid & 1;
    const int g = lane >> 2, tg = lane & 3;

    float acc[2][8][4];
#pragma unroll
    for (int ms = 0; ms < 2; ms++)
#pragma unroll
        for (int ns = 0; ns < 8; ns++)
#pragma unroll
            for (int i = 0; i < 4; i++) acc[ms][ns][i] = 0.0f;

    const __half* Ab = A + (size_t)m0 * K;
    const __half* Bb = B + (size_t)n0 * K;

    auto load_stage = [&](int s, int k0) {
        uint32_t sbase = sb + s * GSTG;
#pragma unroll
        for (int i = 0; i < 4; i++) {
            int idx = tid + i * 256;
            int row = idx >> 3, c = idx & 7;
            cp16(sbase + swz128(row * 128 + c * 16), Ab + (size_t)row * K + k0 + c * 8);
        }
#pragma unroll
        for (int i = 0; i < 4; i++) {
            int idx = tid + i * 256;
            int row = idx >> 3, c = idx & 7;
            cp16(sbase + 16384 + swz128(row * 128 + c * 16), Bb + (size_t)row * K + k0 + c * 8);
        }
        asm volatile("cp.async.commit_group;\n" ::: "memory");
    };

    const int NT = K >> 6;
    load_stage(0, 0);
    load_stage(1, 64);

    const int r16 = lane & 15, chb = (lane >> 4) << 4;   // ldmatrix row / k-half byte

    for (int it = 0; it < NT; ++it) {
        const int s = it % 3;
        if (it == NT - 1) asm volatile("cp.async.wait_group 0;\n" ::: "memory");
        else              asm volatile("cp.async.wait_group 1;\n" ::: "memory");
        __syncthreads();
        if (it + 2 < NT) load_stage((it + 2) % 3, (it + 2) * 64);

        const uint32_t sA = sb + s * GSTG;
        const uint32_t sB = sA + 16384;
#pragma unroll
        for (int kk = 0; kk < 4; kk++) {
            const int kb = kk * 32 + chb;
            uint32_t a[2][4], b[8][2];
#pragma unroll
            for (int ms = 0; ms < 2; ms++) {
                uint32_t ad = sA + swz128(((wr * 32 + ms * 16 + r16) << 7) + kb);
                LDSM4(a[ms][0], a[ms][1], a[ms][2], a[ms][3], ad);
            }
#pragma unroll
            for (int np = 0; np < 4; np++) {
                uint32_t bd = sB + swz128(((wc * 64 + np * 16 + r16) << 7) + kb);
                uint32_t r0, r1, r2, r3;
                LDSM4(r0, r1, r2, r3, bd);
                b[2 * np][0] = r0; b[2 * np + 1][0] = r1;
                b[2 * np][1] = r2; b[2 * np + 1][1] = r3;
            }
#pragma unroll
            for (int ms = 0; ms < 2; ms++)
#pragma unroll
                for (int ns = 0; ns < 8; ns++)
                    mma_f16(acc[ms][ns], a[ms], b[ns]);
        }
        __syncthreads();
    }

#pragma unroll
    for (int ms = 0; ms < 2; ms++)
#pragma unroll
        for (int ns = 0; ns < 8; ns++) {
            int row = m0 + wr * 32 + ms * 16 + g;
            int col = n0 + wc * 64 + ns * 8 + 2 * tg;
            float b0 = bias[col], b1 = bias[col + 1];
#pragma unroll
            for (int h2 = 0; h2 < 2; h2++) {
                int r = row + h2 * 8;
                size_t idx;
                if (trans_out) {
                    int bb = r & 63, tt = r >> 6;
                    idx = ((size_t)bb * TDEC + tt) * (size_t)N + col;
                } else {
                    idx = (size_t)r * (size_t)N + col;
                }
                float2 v;
                v.x = acc[ms][ns][h2 * 2 + 0] + b0;
                v.y = acc[ms][ns][h2 * 2 + 1] + b1;
                *(float2*)(C + idx) = v;
            }
        }
}

// ---------------- small tf32 GEMM (ctx only: 64 x 3072 x 1024) ----------------
__global__ __launch_bounds__(256, 2)
void gemm_tf32_k(const float* __restrict__ A, int lda,
                 const float* __restrict__ W, int ldw, int koff,
                 float* __restrict__ C, int M, int N, int K) {
    __shared__ uint32_t As[128][20];
    __shared__ uint32_t Bs[128][20];
    const int m0 = blockIdx.x * 128, n0 = blockIdx.y * 128;
    const int tid = threadIdx.x, lane = tid & 31, wid = tid >> 5;
    const int wr = wid >> 1, wc = wid & 1;
    const int g = lane >> 2, tg = lane & 3;
    float acc[2][8][4];
#pragma unroll
    for (int ms = 0; ms < 2; ms++)
#pragma unroll
        for (int ns = 0; ns < 8; ns++)
#pragma unroll
            for (int i = 0; i < 4; i++) acc[ms][ns][i] = 0.0f;
    const int lrow = tid >> 1, lcol = (tid & 1) * 8;
    const float* Ap = A + (size_t)(m0 + lrow) * lda + lcol;
    const float* Wp = W + (size_t)(n0 + lrow) * ldw + koff + lcol;
    const bool aok = (m0 + lrow) < M;
    for (int k0 = 0; k0 < K; k0 += 16) {
        if (aok) {
            cvt_store4(&As[lrow][lcol], *(const float4*)(Ap + k0));
            cvt_store4(&As[lrow][lcol + 4], *(const float4*)(Ap + k0 + 4));
        } else {
#pragma unroll
            for (int i = 0; i < 8; i++) As[lrow][lcol + i] = 0u;
        }
        cvt_store4(&Bs[lrow][lcol], *(const float4*)(Wp + k0));
        cvt_store4(&Bs[lrow][lcol + 4], *(const float4*)(Wp + k0 + 4));
        __syncthreads();
#pragma unroll
        for (int kk = 0; kk < 16; kk += 8) {
            uint32_t a[2][4], b[8][2];
#pragma unroll
            for (int ms = 0; ms < 2; ms++) {
                int r0 = wr * 32 + ms * 16 + g;
                a[ms][0] = As[r0][kk + tg]; a[ms][1] = As[r0 + 8][kk + tg];
                a[ms][2] = As[r0][kk + tg + 4]; a[ms][3] = As[r0 + 8][kk + tg + 4];
            }
#pragma unroll
            for (int ns = 0; ns < 8; ns++) {
                int br = wc * 64 + ns * 8 + g;
                b[ns][0] = Bs[br][kk + tg]; b[ns][1] = Bs[br][kk + tg + 4];
            }
#pragma unroll
            for (int ms = 0; ms < 2; ms++)
#pragma unroll
                for (int ns = 0; ns < 8; ns++) mma_tf32(acc[ms][ns], a[ms], b[ns]);
        }
        __syncthreads();
    }
#pragma unroll
    for (int ms = 0; ms < 2; ms++)
#pragma unroll
        for (int ns = 0; ns < 8; ns++) {
            int row = m0 + wr * 32 + ms * 16 + g;
            int col = n0 + wc * 64 + ns * 8 + 2 * tg;
#pragma unroll
            for (int h2 = 0; h2 < 2; h2++) {
                int r = row + h2 * 8;
                if (r < M) {
                    size_t idx = (size_t)r * (size_t)N + col;
                    float2 v;
                    v.x = acc[ms][ns][h2 * 2 + 0];
                    v.y = acc[ms][ns][h2 * 2 + 1];
                    *(float2*)(C + idx) = v;
                }
            }
        }
}

// ---------------- persistent GRU recurrence (fp16 mma) ----------------
template <bool DEC>
__global__ __launch_bounds__(256, 1)
void gru_persistent_k(float* __restrict__ h0, float* __restrict__ h1,
                      const float* __restrict__ Whh, const float* __restrict__ bhh,
                      const float* __restrict__ gi, const float* __restrict__ ctx,
                      __half* __restrict__ st, int T) {
    extern __shared__ uint32_t sm[];
    uint32_t* Wsh = sm;
    uint32_t* Ash = sm + 48 * WSH_STRIDE;
    float* Gsh = (float*)(sm + 48 * WSH_STRIDE);

    const int u0 = blockIdx.x * 16;
    const int tid = threadIdx.x, lane = tid & 31, wid = tid >> 5;
    const int kg = wid >> 2, mg = (wid >> 1) & 1, ng = wid & 1;
    const int g = lane >> 2, tg = lane & 3;

    for (int j = 0; j < 48; j++) {
        int grow = (j >> 4) * H + u0 + (j & 15);
        float4 v = *(const float4*)(Whh + (size_t)grow * H + tid * 4);
        Wsh[j * WSH_STRIDE + tid * 2]     = pack2(v.x, v.y);
        Wsh[j * WSH_STRIDE + tid * 2 + 1] = pack2(v.z, v.w);
    }
    const int sr = tid >> 2, sc0 = (tid & 3) * 4;

    for (int t = 0; t < T; t++) {
        const float* hin = (t & 1) ? h1 : h0;
        float* hout = (t & 1) ? h0 : h1;
        const float* gi_t = gi + (size_t)t * BATCH * 3 * H;

        float4 p0 = *(const float4*)(hin + sr * H + (tid & 3) * 8);
        float4 p1 = *(const float4*)(hin + sr * H + (tid & 3) * 8 + 4);

        float acc[2][3][4];
#pragma unroll
        for (int ms = 0; ms < 2; ms++)
#pragma unroll
            for (int ns = 0; ns < 3; ns++)
#pragma unroll
                for (int i = 0; i < 4; i++) acc[ms][ns][i] = 0.0f;

        for (int c = 0; c < 32; c++) {
            uint32_t* Ab = Ash + (c & 1) * 64 * ASH_STRIDE;
            Ab[sr * ASH_STRIDE + sc0]     = pack2(p0.x, p0.y);
            Ab[sr * ASH_STRIDE + sc0 + 1] = pack2(p0.z, p0.w);
            Ab[sr * ASH_STRIDE + sc0 + 2] = pack2(p1.x, p1.y);
            Ab[sr * ASH_STRIDE + sc0 + 3] = pack2(p1.z, p1.w);
            __syncthreads();
            if (c < 31) {
                p0 = *(const float4*)(hin + sr * H + (c + 1) * 32 + (tid & 3) * 8);
                p1 = *(const float4*)(hin + sr * H + (c + 1) * 32 + (tid & 3) * 8 + 4);
            }
            {
                const int c0 = kg * 8;
                const int wc0 = c * 16 + kg * 8;
                uint32_t a[2][4], b[3][2];
#pragma unroll
                for (int ms = 0; ms < 2; ms++) {
                    int row = mg * 32 + ms * 16 + g;
                    a[ms][0] = Ab[row * ASH_STRIDE + c0 + tg];
                    a[ms][1] = Ab[(row + 8) * ASH_STRIDE + c0 + tg];
                    a[ms][2] = Ab[row * ASH_STRIDE + c0 + tg + 4];
                    a[ms][3] = Ab[(row + 8) * ASH_STRIDE + c0 + tg + 4];
                }
#pragma unroll
                for (int ns = 0; ns < 3; ns++) {
                    int br = ng * 24 + ns * 8 + g;
                    b[ns][0] = Wsh[br * WSH_STRIDE + wc0 + tg];
                    b[ns][1] = Wsh[br * WSH_STRIDE + wc0 + tg + 4];
                }
#pragma unroll
                for (int ms = 0; ms < 2; ms++)
#pragma unroll
                    for (int ns = 0; ns < 3; ns++) mma_f16(acc[ms][ns], a[ms], b[ns]);
            }
        }
        __syncthreads();

#pragma unroll
        for (int ms = 0; ms < 2; ms++)
#pragma unroll
            for (int ns = 0; ns < 3; ns++)
#pragma unroll
                for (int i = 0; i < 4; i++) {
                    int row = mg * 32 + ms * 16 + g + (i >> 1) * 8;
                    int col = ng * 24 + ns * 8 + 2 * tg + (i & 1);
                    Gsh[(kg * 64 + row) * GSH_STRIDE + col] = acc[ms][ns][i];
                }
        __syncthreads();

#pragma unroll
        for (int j = 0; j < 4; j++) {
            int idx = tid + j * 256;
            int b = idx >> 4, ul = idx & 15, u = u0 + ul;
            float aR = Gsh[b * GSH_STRIDE + ul]      + Gsh[(64 + b) * GSH_STRIDE + ul];
            float aZ = Gsh[b * GSH_STRIDE + 16 + ul] + Gsh[(64 + b) * GSH_STRIDE + 16 + ul];
            float aN = Gsh[b * GSH_STRIDE + 32 + ul] + Gsh[(64 + b) * GSH_STRIDE + 32 + ul];
            float gr = gi_t[(size_t)b * 3 * H + u];
            float gz = gi_t[(size_t)b * 3 * H + H + u];
            float gn = gi_t[(size_t)b * 3 * H + 2 * H + u];
            if (DEC) {
                const float* cw = ctx + (size_t)b * 3 * H;
                gr += cw[u]; gz += cw[H + u]; gn += cw[2 * H + u];
            }
            float rr = 1.0f / (1.0f + __expf(-(gr + aR + bhh[u])));
            float zz = 1.0f / (1.0f + __expf(-(gz + aZ + bhh[H + u])));
            float nn = tanhf(gn + rr * (aN + bhh[2 * H + u]));
            float hn = (1.0f - zz) * nn + zz * hin[(size_t)b * H + u];
            hout[(size_t)b * H + u] = hn;
            if (DEC) st[(size_t)t * BATCH * H + (size_t)b * H + u] = __float2half_rn(hn);
        }

        __threadfence();
        __syncthreads();
        if (tid == 0) {
            unsigned old_gen = *(volatile unsigned*)&g_bar_gen;
            unsigned r = atomicAdd(&g_bar_cnt, 1);
            if (r == NCTA - 1) {
                atomicExch(&g_bar_cnt, 0);
                __threadfence();
                atomicAdd(&g_bar_gen, 1);
            } else {
                while (*(volatile unsigned*)&g_bar_gen == old_gen) {}
            }
        }
        __syncthreads();
    }
}

// ---------------- host orchestration ----------------
extern "C" void kernel_launch(void* const* d_in, const int* in_sizes, int n_in,
                              void* d_out, int out_size) {
    const int*   x        = (const int*)d_in[0];
    const int*   labels   = (const int*)d_in[1];
    const int*   bos      = (const int*)d_in[2];
    const float* enc_emb  = (const float*)d_in[3];
    const float* enc_Wih  = (const float*)d_in[4];
    const float* enc_Whh  = (const float*)d_in[5];
    const float* enc_bih  = (const float*)d_in[6];
    const float* enc_bhh  = (const float*)d_in[7];
    const float* dec_emb  = (const float*)d_in[8];
    const float* dec_Wih  = (const float*)d_in[9];
    const float* dec_Whh  = (const float*)d_in[10];
    const float* dec_bih  = (const float*)d_in[11];
    const float* dec_bhh  = (const float*)d_in[12];
    const float* dec_init = (const float*)d_in[13];
    const float* lin_W    = (const float*)d_in[14];
    const float* lin_b    = (const float*)d_in[15];
    float*       out      = (float*)d_out;

    __half *Xe, *Xw, *st, *We, *Wd, *Wl;
    float *Xi, *Xd, *ctx, *h0, *h1, *hd0, *hd1;
    cudaGetSymbolAddress((void**)&Xe, g_Xe);
    cudaGetSymbolAddress((void**)&Xi, g_Xi);
    cudaGetSymbolAddress((void**)&Xw, g_Xw);
    cudaGetSymbolAddress((void**)&Xd, g_Xd);
    cudaGetSymbolAddress((void**)&ctx, g_ctx);
    cudaGetSymbolAddress((void**)&h0, g_h0);
    cudaGetSymbolAddress((void**)&h1, g_h1);
    cudaGetSymbolAddress((void**)&hd0, g_hd0);
    cudaGetSymbolAddress((void**)&hd1, g_hd1);
    cudaGetSymbolAddress((void**)&st, g_st);
    cudaGetSymbolAddress((void**)&We, g_We);
    cudaGetSymbolAddress((void**)&Wd, g_Wd);
    cudaGetSymbolAddress((void**)&Wl, g_Wl);

    cudaFuncSetAttribute(gru_persistent_k<false>,
                         cudaFuncAttributeMaxDynamicSharedMemorySize, GRU_SMEM_BYTES);
    cudaFuncSetAttribute(gru_persistent_k<true>,
                         cudaFuncAttributeMaxDynamicSharedMemorySize, GRU_SMEM_BYTES);
    cudaFuncSetAttribute(gemm_f16_k,
                         cudaFuncAttributeMaxDynamicSharedMemorySize, GEMM_SMEM_BYTES);

    // ---- fp16 weight conversion ----
    conv_k<<<(3 * H * DEMB / 8 + 255) / 256, 256>>>(enc_Wih, We, 3 * H * DEMB / 8);
    conv_slice_k<<<3 * H, 128>>>(dec_Wih, Wd);
    conv_k<<<((size_t)VOCAB * H / 8 + 255) / 256, 256>>>(lin_W, Wl, VOCAB * H / 8);

    // ---- encoder ----
    embed_enc_k<<<TENC * BATCH, 128>>>(x, enc_emb, Xe);
    init_all_k<<<BATCH, H>>>(h0, hd0, dec_init);
    gemm_f16_k<<<dim3(TENC * BATCH / 128, 3 * H / 128), 256, GEMM_SMEM_BYTES>>>(
        Xe, We, enc_bih, Xi, 3 * H, DEMB, 0);
    gru_persistent_k<false><<<NCTA, 256, GRU_SMEM_BYTES>>>(h0, h1, enc_Whh, enc_bhh,
                                                           Xi, nullptr, nullptr, TENC);
    float* efin = h0;

    // ---- decoder precompute ----
    embed_dec_k<<<TDEC * BATCH, 128>>>(labels, bos, dec_emb, Xw);
    gemm_f16_k<<<dim3(TDEC * BATCH / 128, 3 * H / 128), 256, GEMM_SMEM_BYTES>>>(
        Xw, Wd, dec_bih, Xd, 3 * H, DEMB, 0);
    gemm_tf32_k<<<dim3(1, 24), 256>>>(efin, H, dec_Wih, DEMB + H, DEMB, ctx,
                                      BATCH, 3 * H, H);
    gru_persistent_k<true><<<NCTA, 256, GRU_SMEM_BYTES>>>(hd0, hd1, dec_Whh, dec_bhh,
                                                          Xd, ctx, st, TDEC);

    // ---- logits ----
    gemm_f16_k<<<dim3(TDEC * BATCH / 128, VOCAB / 128), 256, GEMM_SMEM_BYTES>>>(
        st, Wl, lin_b, out, VOCAB, H, 1);
}

// round 6
// speedup vs baseline: 3.7827x; 1.3090x over previous
#include <cuda_runtime.h>
#include <cuda_fp16.h>
#include <cstdint>
#include <math.h>

#define H     1024
#define BATCH 64
#define TENC  128
#define TDEC  64
#define VOCAB 32000
#define DEMB  512

// ---------------- persistent-GRU (128 CTAs x 8 units) smem layout ----------------
#define GRU_NCTA 128
#define W2S 516                       // half2 words per Whh row (512 + 4 pad)
#define A2S 36                        // half2 words per h-chunk row (32 + 4 pad)
#define G2S 28                        // fp32 per partial row (24 + 4 pad)
#define GRU_SMEM_WORDS (24 * W2S + 4 * 64 * G2S)   // Gsh(7168) > Ash(2*64*36=4608)
#define GRU_SMEM_BYTES (GRU_SMEM_WORDS * 4)

// ---------------- fp16 GEMM smem: BM128 x BN256 x BK64, 3 stages ----------------
#define GSTG 49152                    // A 16KB + B 32KB
#define GEMM_SMEM_BYTES (3 * GSTG)    // 144KB, 1 CTA/SM

// ---------------- scratch ----------------
__device__ __half g_Xe[(size_t)TENC * BATCH * DEMB];
__device__ float  g_Xi[(size_t)TENC * BATCH * 3 * H];
__device__ __half g_Xw[(size_t)TDEC * BATCH * DEMB];
__device__ float  g_Xd[(size_t)TDEC * BATCH * 3 * H];
__device__ float  g_ctx[(size_t)BATCH * 3 * H];
__device__ float  g_h0f[(size_t)BATCH * H];
__device__ float  g_h1f[(size_t)BATCH * H];
__device__ __half g_h0h[(size_t)BATCH * H];
__device__ __half g_h1h[(size_t)BATCH * H];
__device__ float  g_hd0f[(size_t)BATCH * H];
__device__ float  g_hd1f[(size_t)BATCH * H];
__device__ __half g_hd0h[(size_t)BATCH * H];
__device__ __half g_hd1h[(size_t)BATCH * H];
__device__ __half g_st[(size_t)TDEC * BATCH * H];
__device__ __half g_We[(size_t)3 * H * DEMB];
__device__ __half g_Wd[(size_t)3 * H * DEMB];
__device__ __half g_Wl[(size_t)VOCAB * H];
__device__ unsigned g_bar_cnt;
__device__ unsigned g_bar_gen;

// ---------------- helpers ----------------
__device__ __forceinline__ uint32_t pack2(float x, float y) {
    __half2 h = __floats2half2_rn(x, y);
    return *(uint32_t*)&h;
}
__device__ __forceinline__ uint32_t f2tf32(float f) {
    uint32_t r;
    asm("cvt.rna.tf32.f32 %0, %1;" : "=r"(r) : "f"(f));
    return r;
}
__device__ __forceinline__ void cvt_store4(uint32_t* dst, float4 v) {
    dst[0] = f2tf32(v.x); dst[1] = f2tf32(v.y);
    dst[2] = f2tf32(v.z); dst[3] = f2tf32(v.w);
}
__device__ __forceinline__ void mma_f16(float* c, const uint32_t* a, const uint32_t* b) {
    asm volatile(
        "mma.sync.aligned.m16n8k16.row.col.f32.f16.f16.f32 "
        "{%0,%1,%2,%3}, {%4,%5,%6,%7}, {%8,%9}, {%0,%1,%2,%3};\n"
        : "+f"(c[0]), "+f"(c[1]), "+f"(c[2]), "+f"(c[3])
        : "r"(a[0]), "r"(a[1]), "r"(a[2]), "r"(a[3]), "r"(b[0]), "r"(b[1]));
}
__device__ __forceinline__ void mma_tf32(float* c, const uint32_t* a, const uint32_t* b) {
    asm volatile(
        "mma.sync.aligned.m16n8k8.row.col.f32.tf32.tf32.f32 "
        "{%0,%1,%2,%3}, {%4,%5,%6,%7}, {%8,%9}, {%0,%1,%2,%3};\n"
        : "+f"(c[0]), "+f"(c[1]), "+f"(c[2]), "+f"(c[3])
        : "r"(a[0]), "r"(a[1]), "r"(a[2]), "r"(a[3]), "r"(b[0]), "r"(b[1]));
}
__device__ __forceinline__ uint32_t smem_u32(const void* p) {
    uint32_t a;
    asm("{ .reg .u64 t; cvta.to.shared.u64 t, %1; cvt.u32.u64 %0, t; }" : "=r"(a) : "l"(p));
    return a;
}
__device__ __forceinline__ uint32_t swz128(uint32_t o) { return o ^ ((o >> 3) & 0x70); }
__device__ __forceinline__ void cp16(uint32_t dst, const void* src) {
    asm volatile("cp.async.cg.shared.global [%0], [%1], 16;\n" :: "r"(dst), "l"(src) : "memory");
}
#define LDSM4(r0, r1, r2, r3, addr) \
    asm volatile("ldmatrix.sync.aligned.m8n8.x4.shared.b16 {%0,%1,%2,%3}, [%4];" \
                 : "=r"(r0), "=r"(r1), "=r"(r2), "=r"(r3) : "r"(addr))

// ---------------- weight fp16 conversion ----------------
__global__ void conv_k(const float* __restrict__ src, __half* __restrict__ dst, int n8) {
    int i = blockIdx.x * 256 + threadIdx.x;
    if (i < n8) {
        float4 a = ((const float4*)src)[2 * i];
        float4 b = ((const float4*)src)[2 * i + 1];
        uint4 u;
        u.x = pack2(a.x, a.y); u.y = pack2(a.z, a.w);
        u.z = pack2(b.x, b.y); u.w = pack2(b.z, b.w);
        ((uint4*)dst)[i] = u;
    }
}
__global__ void conv_slice_k(const float* __restrict__ src, __half* __restrict__ dst) {
    int r = blockIdx.x;
    float4 v = ((const float4*)(src + (size_t)r * (DEMB + H)))[threadIdx.x];
    uint2 u; u.x = pack2(v.x, v.y); u.y = pack2(v.z, v.w);
    ((uint2*)(dst + (size_t)r * DEMB))[threadIdx.x] = u;
}

// ---------------- embedding gathers -> fp16 ----------------
__global__ void embed_enc_k(const int* __restrict__ x, const float* __restrict__ emb,
                            __half* __restrict__ Xe) {
    int row = blockIdx.x;
    int t = row >> 6, b = row & 63;
    int tok = x[b * TENC + t];
    float4 v = ((const float4*)(emb + (size_t)tok * DEMB))[threadIdx.x];
    uint2 u; u.x = pack2(v.x, v.y); u.y = pack2(v.z, v.w);
    ((uint2*)(Xe + (size_t)row * DEMB))[threadIdx.x] = u;
}
__global__ void embed_dec_k(const int* __restrict__ labels, const int* __restrict__ bos,
                            const float* __restrict__ emb, __half* __restrict__ Xw) {
    int row = blockIdx.x;
    int t = row >> 6, b = row & 63;
    int tok = (t == 0) ? bos[0] : labels[b * TDEC + t - 1];
    float4 v = ((const float4*)(emb + (size_t)tok * DEMB))[threadIdx.x];
    uint2 u; u.x = pack2(v.x, v.y); u.y = pack2(v.z, v.w);
    ((uint2*)(Xw + (size_t)row * DEMB))[threadIdx.x] = u;
}

__global__ void init_all_k(float* __restrict__ h0f, __half* __restrict__ h0h,
                           float* __restrict__ hd0f, __half* __restrict__ hd0h,
                           const float* __restrict__ dec_init) {
    int b = blockIdx.x, u = threadIdx.x;
    h0f[b * H + u] = 0.0f;
    h0h[b * H + u] = __float2half_rn(0.0f);
    float di = dec_init[u];
    hd0f[b * H + u] = di;
    hd0h[b * H + u] = __float2half_rn(di);
    if (b == 0 && u == 0) { g_bar_cnt = 0; g_bar_gen = 0; }
}

// ---------------- fp16 GEMM: C(MxN fp32) = A(MxK h) @ B(NxK h)^T + bias ----------------
// BM=128, BN=256, BK=64. 1 CTA/SM, 3-stage cp.async, ldmatrix, XOR-swizzle.
// 8 warps: wr = wid>>1 (m, 4), wc = wid&1 (n, 2); warp tile 32x128.
__global__ __launch_bounds__(256, 1)
void gemm_f16_k(const __half* __restrict__ A, const __half* __restrict__ B,
                const float* __restrict__ bias, float* __restrict__ C,
                int N, int K, int trans_out) {
    extern __shared__ char smc[];
    const uint32_t sb = smem_u32(smc);
    const int m0 = blockIdx.x * 128, n0 = blockIdx.y * 256;
    const int tid = threadIdx.x, lane = tid & 31, wid = tid >> 5;
    const int wr = wid >> 1, wc = wid & 1;
    const int g = lane >> 2, tg = lane & 3;

    float acc[2][16][4];
#pragma unroll
    for (int ms = 0; ms < 2; ms++)
#pragma unroll
        for (int ns = 0; ns < 16; ns++)
#pragma unroll
            for (int i = 0; i < 4; i++) acc[ms][ns][i] = 0.0f;

    const __half* Ab = A + (size_t)m0 * K;
    const __half* Bb = B + (size_t)n0 * K;

    auto load_stage = [&](int s, int k0) {
        uint32_t sbase = sb + s * GSTG;
#pragma unroll
        for (int i = 0; i < 4; i++) {            // A: 128 rows
            int idx = tid + i * 256;
            int row = idx >> 3, c = idx & 7;
            cp16(sbase + swz128(row * 128 + c * 16), Ab + (size_t)row * K + k0 + c * 8);
        }
#pragma unroll
        for (int i = 0; i < 8; i++) {            // B: 256 rows
            int idx = tid + i * 256;
            int row = idx >> 3, c = idx & 7;
            cp16(sbase + 16384 + swz128(row * 128 + c * 16), Bb + (size_t)row * K + k0 + c * 8);
        }
        asm volatile("cp.async.commit_group;\n" ::: "memory");
    };

    const int NT = K >> 6;
    load_stage(0, 0);
    load_stage(1, 64);

    const int r16 = lane & 15, chb = (lane >> 4) << 4;

    for (int it = 0; it < NT; ++it) {
        const int s = it % 3;
        if (it == NT - 1) asm volatile("cp.async.wait_group 0;\n" ::: "memory");
        else              asm volatile("cp.async.wait_group 1;\n" ::: "memory");
        __syncthreads();
        if (it + 2 < NT) load_stage((it + 2) % 3, (it + 2) * 64);

        const uint32_t sA = sb + s * GSTG;
        const uint32_t sB = sA + 16384;
#pragma unroll
        for (int kk = 0; kk < 4; kk++) {
            const int kb = kk * 32 + chb;
            uint32_t a[2][4], b[16][2];
#pragma unroll
            for (int ms = 0; ms < 2; ms++) {
                uint32_t ad = sA + swz128(((wr * 32 + ms * 16 + r16) << 7) + kb);
                LDSM4(a[ms][0], a[ms][1], a[ms][2], a[ms][3], ad);
            }
#pragma unroll
            for (int np = 0; np < 8; np++) {
                uint32_t bd = sB + swz128(((wc * 128 + np * 16 + r16) << 7) + kb);
                uint32_t r0, r1, r2, r3;
                LDSM4(r0, r1, r2, r3, bd);
                b[2 * np][0] = r0; b[2 * np + 1][0] = r1;
                b[2 * np][1] = r2; b[2 * np + 1][1] = r3;
            }
#pragma unroll
            for (int ms = 0; ms < 2; ms++)
#pragma unroll
                for (int ns = 0; ns < 16; ns++)
                    mma_f16(acc[ms][ns], a[ms], b[ns]);
        }
        __syncthreads();
    }

#pragma unroll
    for (int ms = 0; ms < 2; ms++)
#pragma unroll
        for (int ns = 0; ns < 16; ns++) {
            int row = m0 + wr * 32 + ms * 16 + g;
            int col = n0 + wc * 128 + ns * 8 + 2 * tg;
            float b0 = bias[col], b1 = bias[col + 1];
#pragma unroll
            for (int h2 = 0; h2 < 2; h2++) {
                int r = row + h2 * 8;
                size_t idx;
                if (trans_out) {
                    int bb = r & 63, tt = r >> 6;
                    idx = ((size_t)bb * TDEC + tt) * (size_t)N + col;
                } else {
                    idx = (size_t)r * (size_t)N + col;
                }
                float2 v;
                v.x = acc[ms][ns][h2 * 2 + 0] + b0;
                v.y = acc[ms][ns][h2 * 2 + 1] + b1;
                *(float2*)(C + idx) = v;
            }
        }
}

// ---------------- small tf32 GEMM (ctx only: 64 x 3072 x 1024) ----------------
__global__ __launch_bounds__(256, 2)
void gemm_tf32_k(const float* __restrict__ A, int lda,
                 const float* __restrict__ W, int ldw, int koff,
                 float* __restrict__ C, int M, int N, int K) {
    __shared__ uint32_t As[128][20];
    __shared__ uint32_t Bs[128][20];
    const int m0 = blockIdx.x * 128, n0 = blockIdx.y * 128;
    const int tid = threadIdx.x, lane = tid & 31, wid = tid >> 5;
    const int wr = wid >> 1, wc = wid & 1;
    const int g = lane >> 2, tg = lane & 3;
    float acc[2][8][4];
#pragma unroll
    for (int ms = 0; ms < 2; ms++)
#pragma unroll
        for (int ns = 0; ns < 8; ns++)
#pragma unroll
            for (int i = 0; i < 4; i++) acc[ms][ns][i] = 0.0f;
    const int lrow = tid >> 1, lcol = (tid & 1) * 8;
    const float* Ap = A + (size_t)(m0 + lrow) * lda + lcol;
    const float* Wp = W + (size_t)(n0 + lrow) * ldw + koff + lcol;
    const bool aok = (m0 + lrow) < M;
    for (int k0 = 0; k0 < K; k0 += 16) {
        if (aok) {
            cvt_store4(&As[lrow][lcol], *(const float4*)(Ap + k0));
            cvt_store4(&As[lrow][lcol + 4], *(const float4*)(Ap + k0 + 4));
        } else {
#pragma unroll
            for (int i = 0; i < 8; i++) As[lrow][lcol + i] = 0u;
        }
        cvt_store4(&Bs[lrow][lcol], *(const float4*)(Wp + k0));
        cvt_store4(&Bs[lrow][lcol + 4], *(const float4*)(Wp + k0 + 4));
        __syncthreads();
#pragma unroll
        for (int kk = 0; kk < 16; kk += 8) {
            uint32_t a[2][4], b[8][2];
#pragma unroll
            for (int ms = 0; ms < 2; ms++) {
                int r0 = wr * 32 + ms * 16 + g;
                a[ms][0] = As[r0][kk + tg]; a[ms][1] = As[r0 + 8][kk + tg];
                a[ms][2] = As[r0][kk + tg + 4]; a[ms][3] = As[r0 + 8][kk + tg + 4];
            }
#pragma unroll
            for (int ns = 0; ns < 8; ns++) {
                int br = wc * 64 + ns * 8 + g;
                b[ns][0] = Bs[br][kk + tg]; b[ns][1] = Bs[br][kk + tg + 4];
            }
#pragma unroll
            for (int ms = 0; ms < 2; ms++)
#pragma unroll
                for (int ns = 0; ns < 8; ns++) mma_tf32(acc[ms][ns], a[ms], b[ns]);
        }
        __syncthreads();
    }
#pragma unroll
    for (int ms = 0; ms < 2; ms++)
#pragma unroll
        for (int ns = 0; ns < 8; ns++) {
            int row = m0 + wr * 32 + ms * 16 + g;
            int col = n0 + wc * 64 + ns * 8 + 2 * tg;
#pragma unroll
            for (int h2 = 0; h2 < 2; h2++) {
                int r = row + h2 * 8;
                if (r < M) {
                    size_t idx = (size_t)r * (size_t)N + col;
                    float2 v;
                    v.x = acc[ms][ns][h2 * 2 + 0];
                    v.y = acc[ms][ns][h2 * 2 + 1];
                    *(float2*)(C + idx) = v;
                }
            }
        }
}

// ---------------- persistent GRU recurrence: 128 CTAs x 8 hidden units ----------------
// h stored dual: fp32 (carry) + fp16 (mma A operand). 8 warps: kg = wid>>1 (4-way K),
// mg = wid&1 (2-way M). Whh slice (24 rows x 1024) resident in smem as half2.
template <bool DEC>
__global__ __launch_bounds__(256, 1)
void gru_persistent_k(float* __restrict__ h0f, float* __restrict__ h1f,
                      __half* __restrict__ h0h, __half* __restrict__ h1h,
                      const float* __restrict__ Whh, const float* __restrict__ bhh,
                      const float* __restrict__ gi, const float* __restrict__ ctx,
                      __half* __restrict__ st, int T) {
    extern __shared__ uint32_t sm[];
    uint32_t* Wsh = sm;                          // [24][W2S] half2 words
    uint32_t* Ash = sm + 24 * W2S;               // [2][64][A2S] half2 words
    float* Gsh = (float*)(sm + 24 * W2S);        // union: [4][64][G2S] fp32

    const int u0 = blockIdx.x * 8;
    const int tid = threadIdx.x, lane = tid & 31, wid = tid >> 5;
    const int kg = wid >> 1, mg = wid & 1;
    const int g = lane >> 2, tg = lane & 3;

    // Whh slice (24 rows) -> smem half2
    for (int j = 0; j < 24; j++) {
        int grow = (j >> 3) * H + u0 + (j & 7);
        float4 v = *(const float4*)(Whh + (size_t)grow * H + tid * 4);
        Wsh[j * W2S + tid * 2]     = pack2(v.x, v.y);
        Wsh[j * W2S + tid * 2 + 1] = pack2(v.z, v.w);
    }
    const int sr = tid >> 2, q = tid & 3;

    for (int t = 0; t < T; t++) {
        const float* hinf = (t & 1) ? h1f : h0f;
        const __half* hinh = (t & 1) ? h1h : h0h;
        float* houtf = (t & 1) ? h0f : h1f;
        __half* houth = (t & 1) ? h0h : h1h;
        const float* gi_t = gi + (size_t)t * BATCH * 3 * H;

        uint4 p0 = *(const uint4*)(hinh + (size_t)sr * H + q * 16);
        uint4 p1 = *(const uint4*)(hinh + (size_t)sr * H + q * 16 + 8);

        float acc[2][3][4];
#pragma unroll
        for (int ms = 0; ms < 2; ms++)
#pragma unroll
            for (int ns = 0; ns < 3; ns++)
#pragma unroll
                for (int i = 0; i < 4; i++) acc[ms][ns][i] = 0.0f;

        for (int c = 0; c < 16; c++) {           // k64 chunks
            uint32_t* Ab = Ash + (c & 1) * 64 * A2S;
            *(uint4*)(Ab + sr * A2S + q * 8)     = p0;
            *(uint4*)(Ab + sr * A2S + q * 8 + 4) = p1;
            __syncthreads();
            if (c < 15) {
                p0 = *(const uint4*)(hinh + (size_t)sr * H + (c + 1) * 64 + q * 16);
                p1 = *(const uint4*)(hinh + (size_t)sr * H + (c + 1) * 64 + q * 16 + 8);
            }
            const int c0 = kg * 8;               // warp's k16 within chunk (half2 cols)
            const int wc0 = c * 32 + kg * 8;     // half2 col in Wsh
            uint32_t a[2][4], b[3][2];
#pragma unroll
            for (int ms = 0; ms < 2; ms++) {
                int row = mg * 32 + ms * 16 + g;
                a[ms][0] = Ab[row * A2S + c0 + tg];
                a[ms][1] = Ab[(row + 8) * A2S + c0 + tg];
                a[ms][2] = Ab[row * A2S + c0 + tg + 4];
                a[ms][3] = Ab[(row + 8) * A2S + c0 + tg + 4];
            }
#pragma unroll
            for (int ns = 0; ns < 3; ns++) {
                int br = ns * 8 + g;
                b[ns][0] = Wsh[br * W2S + wc0 + tg];
                b[ns][1] = Wsh[br * W2S + wc0 + tg + 4];
            }
#pragma unroll
            for (int ms = 0; ms < 2; ms++)
#pragma unroll
                for (int ns = 0; ns < 3; ns++) mma_f16(acc[ms][ns], a[ms], b[ns]);
        }
        __syncthreads();   // mma done; Ash region reused as Gsh

#pragma unroll
        for (int ms = 0; ms < 2; ms++)
#pragma unroll
            for (int ns = 0; ns < 3; ns++)
#pragma unroll
                for (int i = 0; i < 4; i++) {
                    int row = mg * 32 + ms * 16 + g + (i >> 1) * 8;
                    int col = ns * 8 + 2 * tg + (i & 1);
                    Gsh[(kg * 64 + row) * G2S + col] = acc[ms][ns][i];
                }
        __syncthreads();

        // gates: 512 (b,u) pairs, 2 per thread
#pragma unroll
        for (int j = 0; j < 2; j++) {
            int idx = tid + j * 256;
            int b = idx >> 3, ul = idx & 7, u = u0 + ul;
            float aR = 0.f, aZ = 0.f, aN = 0.f;
#pragma unroll
            for (int k = 0; k < 4; k++) {
                const float* Gr = Gsh + (k * 64 + b) * G2S;
                aR += Gr[ul]; aZ += Gr[8 + ul]; aN += Gr[16 + ul];
            }
            float gr = gi_t[(size_t)b * 3 * H + u];
            float gz = gi_t[(size_t)b * 3 * H + H + u];
            float gn = gi_t[(size_t)b * 3 * H + 2 * H + u];
            if (DEC) {
                const float* cw = ctx + (size_t)b * 3 * H;
                gr += cw[u]; gz += cw[H + u]; gn += cw[2 * H + u];
            }
            float rr = 1.0f / (1.0f + __expf(-(gr + aR + bhh[u])));
            float zz = 1.0f / (1.0f + __expf(-(gz + aZ + bhh[H + u])));
            float nn = tanhf(gn + rr * (aN + bhh[2 * H + u]));
            float hn = (1.0f - zz) * nn + zz * hinf[(size_t)b * H + u];
            houtf[(size_t)b * H + u] = hn;
            __half hh = __float2half_rn(hn);
            houth[(size_t)b * H + u] = hh;
            if (DEC) st[(size_t)t * BATCH * H + (size_t)b * H + u] = hh;
        }

        __threadfence();
        __syncthreads();
        if (tid == 0) {
            unsigned old_gen = *(volatile unsigned*)&g_bar_gen;
            unsigned r = atomicAdd(&g_bar_cnt, 1);
            if (r == GRU_NCTA - 1) {
                atomicExch(&g_bar_cnt, 0);
                __threadfence();
                atomicAdd(&g_bar_gen, 1);
            } else {
                while (*(volatile unsigned*)&g_bar_gen == old_gen) {}
            }
        }
        __syncthreads();
    }
}

// ---------------- host orchestration ----------------
extern "C" void kernel_launch(void* const* d_in, const int* in_sizes, int n_in,
                              void* d_out, int out_size) {
    const int*   x        = (const int*)d_in[0];
    const int*   labels   = (const int*)d_in[1];
    const int*   bos      = (const int*)d_in[2];
    const float* enc_emb  = (const float*)d_in[3];
    const float* enc_Wih  = (const float*)d_in[4];
    const float* enc_Whh  = (const float*)d_in[5];
    const float* enc_bih  = (const float*)d_in[6];
    const float* enc_bhh  = (const float*)d_in[7];
    const float* dec_emb  = (const float*)d_in[8];
    const float* dec_Wih  = (const float*)d_in[9];
    const float* dec_Whh  = (const float*)d_in[10];
    const float* dec_bih  = (const float*)d_in[11];
    const float* dec_bhh  = (const float*)d_in[12];
    const float* dec_init = (const float*)d_in[13];
    const float* lin_W    = (const float*)d_in[14];
    const float* lin_b    = (const float*)d_in[15];
    float*       out      = (float*)d_out;

    __half *Xe, *Xw, *st, *We, *Wd, *Wl, *h0h, *h1h, *hd0h, *hd1h;
    float *Xi, *Xd, *ctx, *h0f, *h1f, *hd0f, *hd1f;
    cudaGetSymbolAddress((void**)&Xe, g_Xe);
    cudaGetSymbolAddress((void**)&Xi, g_Xi);
    cudaGetSymbolAddress((void**)&Xw, g_Xw);
    cudaGetSymbolAddress((void**)&Xd, g_Xd);
    cudaGetSymbolAddress((void**)&ctx, g_ctx);
    cudaGetSymbolAddress((void**)&h0f, g_h0f);
    cudaGetSymbolAddress((void**)&h1f, g_h1f);
    cudaGetSymbolAddress((void**)&h0h, g_h0h);
    cudaGetSymbolAddress((void**)&h1h, g_h1h);
    cudaGetSymbolAddress((void**)&hd0f, g_hd0f);
    cudaGetSymbolAddress((void**)&hd1f, g_hd1f);
    cudaGetSymbolAddress((void**)&hd0h, g_hd0h);
    cudaGetSymbolAddress((void**)&hd1h, g_hd1h);
    cudaGetSymbolAddress((void**)&st, g_st);
    cudaGetSymbolAddress((void**)&We, g_We);
    cudaGetSymbolAddress((void**)&Wd, g_Wd);
    cudaGetSymbolAddress((void**)&Wl, g_Wl);

    cudaFuncSetAttribute(gru_persistent_k<false>,
                         cudaFuncAttributeMaxDynamicSharedMemorySize, GRU_SMEM_BYTES);
    cudaFuncSetAttribute(gru_persistent_k<true>,
                         cudaFuncAttributeMaxDynamicSharedMemorySize, GRU_SMEM_BYTES);
    cudaFuncSetAttribute(gemm_f16_k,
                         cudaFuncAttributeMaxDynamicSharedMemorySize, GEMM_SMEM_BYTES);

    // ---- fp16 weight conversion ----
    conv_k<<<(3 * H * DEMB / 8 + 255) / 256, 256>>>(enc_Wih, We, 3 * H * DEMB / 8);
    conv_slice_k<<<3 * H, 128>>>(dec_Wih, Wd);
    conv_k<<<((size_t)VOCAB * H / 8 + 255) / 256, 256>>>(lin_W, Wl, VOCAB * H / 8);

    // ---- encoder ----
    embed_enc_k<<<TENC * BATCH, 128>>>(x, enc_emb, Xe);
    init_all_k<<<BATCH, H>>>(h0f, h0h, hd0f, hd0h, dec_init);
    gemm_f16_k<<<dim3(TENC * BATCH / 128, 3 * H / 256), 256, GEMM_SMEM_BYTES>>>(
        Xe, We, enc_bih, Xi, 3 * H, DEMB, 0);
    gru_persistent_k<false><<<GRU_NCTA, 256, GRU_SMEM_BYTES>>>(
        h0f, h1f, h0h, h1h, enc_Whh, enc_bhh, Xi, nullptr, nullptr, TENC);
    float* efin = h0f;   // TENC even -> final state in h0f

    // ---- decoder precompute ----
    embed_dec_k<<<TDEC * BATCH, 128>>>(labels, bos, dec_emb, Xw);
    gemm_f16_k<<<dim3(TDEC * BATCH / 128, 3 * H / 256), 256, GEMM_SMEM_BYTES>>>(
        Xw, Wd, dec_bih, Xd, 3 * H, DEMB, 0);
    gemm_tf32_k<<<dim3(1, 24), 256>>>(efin, H, dec_Wih, DEMB + H, DEMB, ctx,
                                      BATCH, 3 * H, H);
    gru_persistent_k<true><<<GRU_NCTA, 256, GRU_SMEM_BYTES>>>(
        hd0f, hd1f, hd0h, hd1h, dec_Whh, dec_bhh, Xd, ctx, st, TDEC);

    // ---- logits ----
    gemm_f16_k<<<dim3(TDEC * BATCH / 128, VOCAB / 256), 256, GEMM_SMEM_BYTES>>>(
        st, Wl, lin_b, out, VOCAB, H, 1);
}

// round 10
// speedup vs baseline: 4.1118x; 1.0870x over previous
#include <cuda_runtime.h>
#include <cuda_fp16.h>
#include <cstdint>
#include <math.h>

#define H     1024
#define BATCH 64
#define TENC  128
#define TDEC  64
#define VOCAB 32000
#define DEMB  512

// ---------------- persistent-GRU (128 CTAs x 8 units) smem layout ----------------
#define GRU_NCTA 128
#define W2S 516                       // half2 words per Whh row (512 + 4 pad)
#define A2S 68                        // half2 words per h-chunk row (64 + 4 pad)
#define G2S 28                        // fp32 per partial row (24 + 4 pad)
#define GRU_SMEM_WORDS (24 * W2S + 2 * 64 * A2S)   // Ash(8704) > Gsh(4*64*28=7168)
#define GRU_SMEM_BYTES (GRU_SMEM_WORDS * 4)

// ---------------- fp16 GEMM smem: BM128 x BN256 x BK64, 3 stages, 512 thr ----------------
#define GSTG 49152                    // A 16KB + B 32KB
#define GEMM_SMEM_BYTES (3 * GSTG)    // 144KB, 1 CTA/SM

// ---------------- scratch ----------------
__device__ __half g_Xe[(size_t)TENC * BATCH * DEMB];
__device__ float  g_Xi[(size_t)TENC * BATCH * 3 * H];
__device__ __half g_Xw[(size_t)TDEC * BATCH * DEMB];
__device__ float  g_Xd[(size_t)TDEC * BATCH * 3 * H];
__device__ float  g_ctx[(size_t)BATCH * 3 * H];
__device__ float  g_h0f[(size_t)BATCH * H];
__device__ float  g_h1f[(size_t)BATCH * H];
__device__ __half g_h0h[(size_t)BATCH * H];
__device__ __half g_h1h[(size_t)BATCH * H];
__device__ float  g_hd0f[(size_t)BATCH * H];
__device__ float  g_hd1f[(size_t)BATCH * H];
__device__ __half g_hd0h[(size_t)BATCH * H];
__device__ __half g_hd1h[(size_t)BATCH * H];
__device__ __half g_st[(size_t)TDEC * BATCH * H];
__device__ __half g_We[(size_t)3 * H * DEMB];
__device__ __half g_Wd[(size_t)3 * H * DEMB];
__device__ __half g_Wl[(size_t)VOCAB * H];
__device__ unsigned g_bar_cnt;
__device__ unsigned g_bar_gen;

// ---------------- helpers ----------------
__device__ __forceinline__ uint32_t pack2(float x, float y) {
    __half2 h = __floats2half2_rn(x, y);
    return *(uint32_t*)&h;
}
__device__ __forceinline__ uint32_t f2tf32(float f) {
    uint32_t r;
    asm("cvt.rna.tf32.f32 %0, %1;" : "=r"(r) : "f"(f));
    return r;
}
__device__ __forceinline__ void cvt_store4(uint32_t* dst, float4 v) {
    dst[0] = f2tf32(v.x); dst[1] = f2tf32(v.y);
    dst[2] = f2tf32(v.z); dst[3] = f2tf32(v.w);
}
__device__ __forceinline__ void mma_f16(float* c, const uint32_t* a, const uint32_t* b) {
    asm volatile(
        "mma.sync.aligned.m16n8k16.row.col.f32.f16.f16.f32 "
        "{%0,%1,%2,%3}, {%4,%5,%6,%7}, {%8,%9}, {%0,%1,%2,%3};\n"
        : "+f"(c[0]), "+f"(c[1]), "+f"(c[2]), "+f"(c[3])
        : "r"(a[0]), "r"(a[1]), "r"(a[2]), "r"(a[3]), "r"(b[0]), "r"(b[1]));
}
__device__ __forceinline__ void mma_tf32(float* c, const uint32_t* a, const uint32_t* b) {
    asm volatile(
        "mma.sync.aligned.m16n8k8.row.col.f32.tf32.tf32.f32 "
        "{%0,%1,%2,%3}, {%4,%5,%6,%7}, {%8,%9}, {%0,%1,%2,%3};\n"
        : "+f"(c[0]), "+f"(c[1]), "+f"(c[2]), "+f"(c[3])
        : "r"(a[0]), "r"(a[1]), "r"(a[2]), "r"(a[3]), "r"(b[0]), "r"(b[1]));
}
__device__ __forceinline__ uint32_t smem_u32(const void* p) {
    uint32_t a;
    asm("{ .reg .u64 t; cvta.to.shared.u64 t, %1; cvt.u32.u64 %0, t; }" : "=r"(a) : "l"(p));
    return a;
}
__device__ __forceinline__ uint32_t swz128(uint32_t o) { return o ^ ((o >> 3) & 0x70); }
__device__ __forceinline__ void cp16(uint32_t dst, const void* src) {
    asm volatile("cp.async.cg.shared.global [%0], [%1], 16;\n" :: "r"(dst), "l"(src) : "memory");
}
#define LDSM4(r0, r1, r2, r3, addr) \
    asm volatile("ldmatrix.sync.aligned.m8n8.x4.shared.b16 {%0,%1,%2,%3}, [%4];" \
                 : "=r"(r0), "=r"(r1), "=r"(r2), "=r"(r3) : "r"(addr))

// ---------------- weight fp16 conversion ----------------
__global__ void conv_k(const float* __restrict__ src, __half* __restrict__ dst, int n8) {
    int i = blockIdx.x * 256 + threadIdx.x;
    if (i < n8) {
        float4 a = ((const float4*)src)[2 * i];
        float4 b = ((const float4*)src)[2 * i + 1];
        uint4 u;
        u.x = pack2(a.x, a.y); u.y = pack2(a.z, a.w);
        u.z = pack2(b.x, b.y); u.w = pack2(b.z, b.w);
        ((uint4*)dst)[i] = u;
    }
}
__global__ void conv_slice_k(const float* __restrict__ src, __half* __restrict__ dst) {
    int r = blockIdx.x;
    float4 v = ((const float4*)(src + (size_t)r * (DEMB + H)))[threadIdx.x];
    uint2 u; u.x = pack2(v.x, v.y); u.y = pack2(v.z, v.w);
    ((uint2*)(dst + (size_t)r * DEMB))[threadIdx.x] = u;
}

// ---------------- embedding gathers -> fp16 ----------------
__global__ void embed_enc_k(const int* __restrict__ x, const float* __restrict__ emb,
                            __half* __restrict__ Xe) {
    int row = blockIdx.x;
    int t = row >> 6, b = row & 63;
    int tok = x[b * TENC + t];
    float4 v = ((const float4*)(emb + (size_t)tok * DEMB))[threadIdx.x];
    uint2 u; u.x = pack2(v.x, v.y); u.y = pack2(v.z, v.w);
    ((uint2*)(Xe + (size_t)row * DEMB))[threadIdx.x] = u;
}
__global__ void embed_dec_k(const int* __restrict__ labels, const int* __restrict__ bos,
                            const float* __restrict__ emb, __half* __restrict__ Xw) {
    int row = blockIdx.x;
    int t = row >> 6, b = row & 63;
    int tok = (t == 0) ? bos[0] : labels[b * TDEC + t - 1];
    float4 v = ((const float4*)(emb + (size_t)tok * DEMB))[threadIdx.x];
    uint2 u; u.x = pack2(v.x, v.y); u.y = pack2(v.z, v.w);
    ((uint2*)(Xw + (size_t)row * DEMB))[threadIdx.x] = u;
}

__global__ void init_all_k(float* __restrict__ h0f, __half* __restrict__ h0h,
                           float* __restrict__ hd0f, __half* __restrict__ hd0h,
                           const float* __restrict__ dec_init) {
    int b = blockIdx.x, u = threadIdx.x;
    h0f[b * H + u] = 0.0f;
    h0h[b * H + u] = __float2half_rn(0.0f);
    float di = dec_init[u];
    hd0f[b * H + u] = di;
    hd0h[b * H + u] = __float2half_rn(di);
    if (b == 0 && u == 0) { g_bar_cnt = 0; g_bar_gen = 0; }
}

// ---------------- fp16 GEMM: C(MxN fp32) = A(MxK h) @ B(NxK h)^T + bias ----------------
// BM=128, BN=256, BK=64. 512 threads (16 warps: wr=wid>>2 m4, wc=wid&3 n4),
// warp tile 32x64. 3-stage cp.async, ldmatrix, XOR-swizzle. 1 CTA/SM.
__global__ __launch_bounds__(512, 1)
void gemm_f16_k(const __half* __restrict__ A, const __half* __restrict__ B,
                const float* __restrict__ bias, float* __restrict__ C,
                int N, int K, int trans_out) {
    extern __shared__ char smc[];
    const uint32_t sb = smem_u32(smc);
    const int m0 = blockIdx.x * 128, n0 = blockIdx.y * 256;
    const int tid = threadIdx.x, lane = tid & 31, wid = tid >> 5;
    const int wr = wid >> 2, wc = wid & 3;
    const int g = lane >> 2, tg = lane & 3;

    float acc[2][8][4];
#pragma unroll
    for (int ms = 0; ms < 2; ms++)
#pragma unroll
        for (int ns = 0; ns < 8; ns++)
#pragma unroll
            for (int i = 0; i < 4; i++) acc[ms][ns][i] = 0.0f;

    const __half* Ab = A + (size_t)m0 * K;
    const __half* Bb = B + (size_t)n0 * K;

    auto load_stage = [&](int s, int k0) {
        uint32_t sbase = sb + s * GSTG;
#pragma unroll
        for (int i = 0; i < 2; i++) {            // A: 128 rows x 64 halves
            int idx = tid + i * 512;
            int row = idx >> 3, c = idx & 7;
            cp16(sbase + swz128(row * 128 + c * 16), Ab + (size_t)row * K + k0 + c * 8);
        }
#pragma unroll
        for (int i = 0; i < 4; i++) {            // B: 256 rows
            int idx = tid + i * 512;
            int row = idx >> 3, c = idx & 7;
            cp16(sbase + 16384 + swz128(row * 128 + c * 16), Bb + (size_t)row * K + k0 + c * 8);
        }
        asm volatile("cp.async.commit_group;\n" ::: "memory");
    };

    const int NT = K >> 6;
    load_stage(0, 0);
    load_stage(1, 64);

    const int r16 = lane & 15, chb = (lane >> 4) << 4;

    for (int it = 0; it < NT; ++it) {
        const int s = it % 3;
        if (it == NT - 1) asm volatile("cp.async.wait_group 0;\n" ::: "memory");
        else              asm volatile("cp.async.wait_group 1;\n" ::: "memory");
        __syncthreads();
        if (it + 2 < NT) load_stage((it + 2) % 3, (it + 2) * 64);

        const uint32_t sA = sb + s * GSTG;
        const uint32_t sB = sA + 16384;
#pragma unroll
        for (int kk = 0; kk < 4; kk++) {
            const int kb = kk * 32 + chb;
            uint32_t a[2][4], b[8][2];
#pragma unroll
            for (int ms = 0; ms < 2; ms++) {
                uint32_t ad = sA + swz128(((wr * 32 + ms * 16 + r16) << 7) + kb);
                LDSM4(a[ms][0], a[ms][1], a[ms][2], a[ms][3], ad);
            }
#pragma unroll
            for (int np = 0; np < 4; np++) {
                uint32_t bd = sB + swz128(((wc * 64 + np * 16 + r16) << 7) + kb);
                uint32_t r0, r1, r2, r3;
                LDSM4(r0, r1, r2, r3, bd);
                b[2 * np][0] = r0; b[2 * np + 1][0] = r1;
                b[2 * np][1] = r2; b[2 * np + 1][1] = r3;
            }
#pragma unroll
            for (int ms = 0; ms < 2; ms++)
#pragma unroll
                for (int ns = 0; ns < 8; ns++)
                    mma_f16(acc[ms][ns], a[ms], b[ns]);
        }
        __syncthreads();
    }

#pragma unroll
    for (int ms = 0; ms < 2; ms++)
#pragma unroll
        for (int ns = 0; ns < 8; ns++) {
            int row = m0 + wr * 32 + ms * 16 + g;
            int col = n0 + wc * 64 + ns * 8 + 2 * tg;
            float b0 = bias[col], b1 = bias[col + 1];
#pragma unroll
            for (int h2 = 0; h2 < 2; h2++) {
                int r = row + h2 * 8;
                size_t idx;
                if (trans_out) {
                    int bb = r & 63, tt = r >> 6;
                    idx = ((size_t)bb * TDEC + tt) * (size_t)N + col;
                } else {
                    idx = (size_t)r * (size_t)N + col;
                }
                float2 v;
                v.x = acc[ms][ns][h2 * 2 + 0] + b0;
                v.y = acc[ms][ns][h2 * 2 + 1] + b1;
                *(float2*)(C + idx) = v;
            }
        }
}

// ---------------- small tf32 GEMM (ctx only: 64 x 3072 x 1024) ----------------
__global__ __launch_bounds__(256, 2)
void gemm_tf32_k(const float* __restrict__ A, int lda,
                 const float* __restrict__ W, int ldw, int koff,
                 float* __restrict__ C, int M, int N, int K) {
    __shared__ uint32_t As[128][20];
    __shared__ uint32_t Bs[128][20];
    const int m0 = blockIdx.x * 128, n0 = blockIdx.y * 128;
    const int tid = threadIdx.x, lane = tid & 31, wid = tid >> 5;
    const int wr = wid >> 1, wc = wid & 1;
    const int g = lane >> 2, tg = lane & 3;
    float acc[2][8][4];
#pragma unroll
    for (int ms = 0; ms < 2; ms++)
#pragma unroll
        for (int ns = 0; ns < 8; ns++)
#pragma unroll
            for (int i = 0; i < 4; i++) acc[ms][ns][i] = 0.0f;
    const int lrow = tid >> 1, lcol = (tid & 1) * 8;
    const float* Ap = A + (size_t)(m0 + lrow) * lda + lcol;
    const float* Wp = W + (size_t)(n0 + lrow) * ldw + koff + lcol;
    const bool aok = (m0 + lrow) < M;
    for (int k0 = 0; k0 < K; k0 += 16) {
        if (aok) {
            cvt_store4(&As[lrow][lcol], *(const float4*)(Ap + k0));
            cvt_store4(&As[lrow][lcol + 4], *(const float4*)(Ap + k0 + 4));
        } else {
#pragma unroll
            for (int i = 0; i < 8; i++) As[lrow][lcol + i] = 0u;
        }
        cvt_store4(&Bs[lrow][lcol], *(const float4*)(Wp + k0));
        cvt_store4(&Bs[lrow][lcol + 4], *(const float4*)(Wp + k0 + 4));
        __syncthreads();
#pragma unroll
        for (int kk = 0; kk < 16; kk += 8) {
            uint32_t a[2][4], b[8][2];
#pragma unroll
            for (int ms = 0; ms < 2; ms++) {
                int r0 = wr * 32 + ms * 16 + g;
                a[ms][0] = As[r0][kk + tg]; a[ms][1] = As[r0 + 8][kk + tg];
                a[ms][2] = As[r0][kk + tg + 4]; a[ms][3] = As[r0 + 8][kk + tg + 4];
            }
#pragma unroll
            for (int ns = 0; ns < 8; ns++) {
                int br = wc * 64 + ns * 8 + g;
                b[ns][0] = Bs[br][kk + tg]; b[ns][1] = Bs[br][kk + tg + 4];
            }
#pragma unroll
            for (int ms = 0; ms < 2; ms++)
#pragma unroll
                for (int ns = 0; ns < 8; ns++) mma_tf32(acc[ms][ns], a[ms], b[ns]);
        }
        __syncthreads();
    }
#pragma unroll
    for (int ms = 0; ms < 2; ms++)
#pragma unroll
        for (int ns = 0; ns < 8; ns++) {
            int row = m0 + wr * 32 + ms * 16 + g;
            int col = n0 + wc * 64 + ns * 8 + 2 * tg;
#pragma unroll
            for (int h2 = 0; h2 < 2; h2++) {
                int r = row + h2 * 8;
                if (r < M) {
                    size_t idx = (size_t)r * (size_t)N + col;
                    float2 v;
                    v.x = acc[ms][ns][h2 * 2 + 0];
                    v.y = acc[ms][ns][h2 * 2 + 1];
                    *(float2*)(C + idx) = v;
                }
            }
        }
}

// ---------------- persistent GRU recurrence: 128 CTAs x 8 hidden units ----------------
// K-chunks of 128 (8 syncs/step); gate inputs prefetched before mma loop.
// NOTE: ctx_r/ctx_z fold into the sigmoid biases (additive), but ctx_n must stay
// OUTSIDE the r*(...) product: n = tanh((i_n + ctx_n) + r*(h@Whh_n + bhh_n)).
template <bool DEC>
__global__ __launch_bounds__(256, 1)
void gru_persistent_k(float* __restrict__ h0f, float* __restrict__ h1f,
                      __half* __restrict__ h0h, __half* __restrict__ h1h,
                      const float* __restrict__ Whh, const float* __restrict__ bhh,
                      const float* __restrict__ gi, const float* __restrict__ ctx,
                      __half* __restrict__ st, int T) {
    extern __shared__ uint32_t sm[];
    uint32_t* Wsh = sm;                          // [24][W2S] half2 words
    uint32_t* Ash = sm + 24 * W2S;               // [2][64][A2S] half2 words
    float* Gsh = (float*)(sm + 24 * W2S);        // union: [4][64][G2S] fp32

    const int u0 = blockIdx.x * 8;
    const int tid = threadIdx.x, lane = tid & 31, wid = tid >> 5;
    const int kg = wid >> 1, mg = wid & 1;
    const int g = lane >> 2, tg = lane & 3;

    // Whh slice (24 rows) -> smem half2
    for (int j = 0; j < 24; j++) {
        int grow = (j >> 3) * H + u0 + (j & 7);
        float4 v = *(const float4*)(Whh + (size_t)grow * H + tid * 4);
        Wsh[j * W2S + tid * 2]     = pack2(v.x, v.y);
        Wsh[j * W2S + tid * 2 + 1] = pack2(v.z, v.w);
    }
    const int sr = tid >> 2, q = tid & 3;
    // gate-phase indices (2 (b,u) pairs per thread)
    const int gb0 = tid >> 3, gu0 = tid & 7;
    const int gb1 = (tid + 256) >> 3, gu1 = (tid + 256) & 7;

    // gate bias (constant over t) in regs. ctx_n kept separate (additive outside r*()).
    float bR0 = bhh[u0 + gu0], bZ0 = bhh[H + u0 + gu0], bN0 = bhh[2 * H + u0 + gu0];
    float bR1 = bhh[u0 + gu1], bZ1 = bhh[H + u0 + gu1], bN1 = bhh[2 * H + u0 + gu1];
    float cN0 = 0.0f, cN1 = 0.0f;
    if (DEC) {
        bR0 += ctx[(size_t)gb0 * 3 * H + u0 + gu0];
        bZ0 += ctx[(size_t)gb0 * 3 * H + H + u0 + gu0];
        cN0  = ctx[(size_t)gb0 * 3 * H + 2 * H + u0 + gu0];
        bR1 += ctx[(size_t)gb1 * 3 * H + u0 + gu1];
        bZ1 += ctx[(size_t)gb1 * 3 * H + H + u0 + gu1];
        cN1  = ctx[(size_t)gb1 * 3 * H + 2 * H + u0 + gu1];
    }

    for (int t = 0; t < T; t++) {
        const float* hinf = (t & 1) ? h1f : h0f;
        const __half* hinh = (t & 1) ? h1h : h0h;
        float* houtf = (t & 1) ? h0f : h1f;
        __half* houth = (t & 1) ? h0h : h1h;
        const float* gi_t = gi + (size_t)t * BATCH * 3 * H;

        // ---- prefetch gate inputs (independent of this step's mma) ----
        float pR0 = gi_t[(size_t)gb0 * 3 * H + u0 + gu0];
        float pZ0 = gi_t[(size_t)gb0 * 3 * H + H + u0 + gu0];
        float pN0 = gi_t[(size_t)gb0 * 3 * H + 2 * H + u0 + gu0];
        float pR1 = gi_t[(size_t)gb1 * 3 * H + u0 + gu1];
        float pZ1 = gi_t[(size_t)gb1 * 3 * H + H + u0 + gu1];
        float pN1 = gi_t[(size_t)gb1 * 3 * H + 2 * H + u0 + gu1];
        float hc0 = hinf[(size_t)gb0 * H + u0 + gu0];
        float hc1 = hinf[(size_t)gb1 * H + u0 + gu1];

        uint4 p[4];
        {
            const uint4* src = (const uint4*)(hinh + (size_t)sr * H + q * 32);
#pragma unroll
            for (int i = 0; i < 4; i++) p[i] = src[i];
        }

        float acc[2][3][4];
#pragma unroll
        for (int ms = 0; ms < 2; ms++)
#pragma unroll
            for (int ns = 0; ns < 3; ns++)
#pragma unroll
                for (int i = 0; i < 4; i++) acc[ms][ns][i] = 0.0f;

        for (int c = 0; c < 8; c++) {            // k128 chunks
            uint32_t* Ab = Ash + (c & 1) * 64 * A2S;
            {
                uint4* dst = (uint4*)(Ab + sr * A2S + q * 16);
#pragma unroll
                for (int i = 0; i < 4; i++) dst[i] = p[i];
            }
            __syncthreads();
            if (c < 7) {
                const uint4* src = (const uint4*)(hinh + (size_t)sr * H + (c + 1) * 128 + q * 32);
#pragma unroll
                for (int i = 0; i < 4; i++) p[i] = src[i];
            }
#pragma unroll
            for (int s = 0; s < 2; s++) {        // warp's two k16 sub-steps
                const int c0 = kg * 16 + s * 8;          // half2 col in Ab
                const int wc0 = c * 64 + kg * 16 + s * 8; // half2 col in Wsh
                uint32_t a[2][4], b[3][2];
#pragma unroll
                for (int ms = 0; ms < 2; ms++) {
                    int row = mg * 32 + ms * 16 + g;
                    a[ms][0] = Ab[row * A2S + c0 + tg];
                    a[ms][1] = Ab[(row + 8) * A2S + c0 + tg];
                    a[ms][2] = Ab[row * A2S + c0 + tg + 4];
                    a[ms][3] = Ab[(row + 8) * A2S + c0 + tg + 4];
                }
#pragma unroll
                for (int ns = 0; ns < 3; ns++) {
                    int br = ns * 8 + g;
                    b[ns][0] = Wsh[br * W2S + wc0 + tg];
                    b[ns][1] = Wsh[br * W2S + wc0 + tg + 4];
                }
#pragma unroll
                for (int ms = 0; ms < 2; ms++)
#pragma unroll
                    for (int ns = 0; ns < 3; ns++) mma_f16(acc[ms][ns], a[ms], b[ns]);
            }
        }
        __syncthreads();   // mma done; Ash region reused as Gsh

#pragma unroll
        for (int ms = 0; ms < 2; ms++)
#pragma unroll
            for (int ns = 0; ns < 3; ns++)
#pragma unroll
                for (int i = 0; i < 4; i++) {
                    int row = mg * 32 + ms * 16 + g + (i >> 1) * 8;
                    int col = ns * 8 + 2 * tg + (i & 1);
                    Gsh[(kg * 64 + row) * G2S + col] = acc[ms][ns][i];
                }
        __syncthreads();

        // gates: 512 (b,u) pairs, 2 per thread, inputs already in regs
        {
            float aR = 0.f, aZ = 0.f, aN = 0.f;
#pragma unroll
            for (int k = 0; k < 4; k++) {
                const float* Gr = Gsh + (k * 64 + gb0) * G2S;
                aR += Gr[gu0]; aZ += Gr[8 + gu0]; aN += Gr[16 + gu0];
            }
            float rr = 1.0f / (1.0f + __expf(-(pR0 + aR + bR0)));
            float zz = 1.0f / (1.0f + __expf(-(pZ0 + aZ + bZ0)));
            float nn = tanhf(pN0 + cN0 + rr * (aN + bN0));
            float hn = (1.0f - zz) * nn + zz * hc0;
            int u = u0 + gu0;
            houtf[(size_t)gb0 * H + u] = hn;
            __half hh = __float2half_rn(hn);
            houth[(size_t)gb0 * H + u] = hh;
            if (DEC) st[(size_t)t * BATCH * H + (size_t)gb0 * H + u] = hh;
        }
        {
            float aR = 0.f, aZ = 0.f, aN = 0.f;
#pragma unroll
            for (int k = 0; k < 4; k++) {
                const float* Gr = Gsh + (k * 64 + gb1) * G2S;
                aR += Gr[gu1]; aZ += Gr[8 + gu1]; aN += Gr[16 + gu1];
            }
            float rr = 1.0f / (1.0f + __expf(-(pR1 + aR + bR1)));
            float zz = 1.0f / (1.0f + __expf(-(pZ1 + aZ + bZ1)));
            float nn = tanhf(pN1 + cN1 + rr * (aN + bN1));
            float hn = (1.0f - zz) * nn + zz * hc1;
            int u = u0 + gu1;
            houtf[(size_t)gb1 * H + u] = hn;
            __half hh = __float2half_rn(hn);
            houth[(size_t)gb1 * H + u] = hh;
            if (DEC) st[(size_t)t * BATCH * H + (size_t)gb1 * H + u] = hh;
        }

        __threadfence();
        __syncthreads();
        if (tid == 0) {
            unsigned old_gen = *(volatile unsigned*)&g_bar_gen;
            unsigned r = atomicAdd(&g_bar_cnt, 1);
            if (r == GRU_NCTA - 1) {
                atomicExch(&g_bar_cnt, 0);
                __threadfence();
                atomicAdd(&g_bar_gen, 1);
            } else {
                while (*(volatile unsigned*)&g_bar_gen == old_gen) {}
            }
        }
        __syncthreads();
    }
}

// ---------------- host orchestration ----------------
extern "C" void kernel_launch(void* const* d_in, const int* in_sizes, int n_in,
                              void* d_out, int out_size) {
    const int*   x        = (const int*)d_in[0];
    const int*   labels   = (const int*)d_in[1];
    const int*   bos      = (const int*)d_in[2];
    const float* enc_emb  = (const float*)d_in[3];
    const float* enc_Wih  = (const float*)d_in[4];
    const float* enc_Whh  = (const float*)d_in[5];
    const float* enc_bih  = (const float*)d_in[6];
    const float* enc_bhh  = (const float*)d_in[7];
    const float* dec_emb  = (const float*)d_in[8];
    const float* dec_Wih  = (const float*)d_in[9];
    const float* dec_Whh  = (const float*)d_in[10];
    const float* dec_bih  = (const float*)d_in[11];
    const float* dec_bhh  = (const float*)d_in[12];
    const float* dec_init = (const float*)d_in[13];
    const float* lin_W    = (const float*)d_in[14];
    const float* lin_b    = (const float*)d_in[15];
    float*       out      = (float*)d_out;

    __half *Xe, *Xw, *st, *We, *Wd, *Wl, *h0h, *h1h, *hd0h, *hd1h;
    float *Xi, *Xd, *ctx, *h0f, *h1f, *hd0f, *hd1f;
    cudaGetSymbolAddress((void**)&Xe, g_Xe);
    cudaGetSymbolAddress((void**)&Xi, g_Xi);
    cudaGetSymbolAddress((void**)&Xw, g_Xw);
    cudaGetSymbolAddress((void**)&Xd, g_Xd);
    cudaGetSymbolAddress((void**)&ctx, g_ctx);
    cudaGetSymbolAddress((void**)&h0f, g_h0f);
    cudaGetSymbolAddress((void**)&h1f, g_h1f);
    cudaGetSymbolAddress((void**)&h0h, g_h0h);
    cudaGetSymbolAddress((void**)&h1h, g_h1h);
    cudaGetSymbolAddress((void**)&hd0f, g_hd0f);
    cudaGetSymbolAddress((void**)&hd1f, g_hd1f);
    cudaGetSymbolAddress((void**)&hd0h, g_hd0h);
    cudaGetSymbolAddress((void**)&hd1h, g_hd1h);
    cudaGetSymbolAddress((void**)&st, g_st);
    cudaGetSymbolAddress((void**)&We, g_We);
    cudaGetSymbolAddress((void**)&Wd, g_Wd);
    cudaGetSymbolAddress((void**)&Wl, g_Wl);

    cudaFuncSetAttribute(gru_persistent_k<false>,
                         cudaFuncAttributeMaxDynamicSharedMemorySize, GRU_SMEM_BYTES);
    cudaFuncSetAttribute(gru_persistent_k<true>,
                         cudaFuncAttributeMaxDynamicSharedMemorySize, GRU_SMEM_BYTES);
    cudaFuncSetAttribute(gemm_f16_k,
                         cudaFuncAttributeMaxDynamicSharedMemorySize, GEMM_SMEM_BYTES);

    // ---- fp16 weight conversion ----
    conv_k<<<(3 * H * DEMB / 8 + 255) / 256, 256>>>(enc_Wih, We, 3 * H * DEMB / 8);
    conv_slice_k<<<3 * H, 128>>>(dec_Wih, Wd);
    conv_k<<<((size_t)VOCAB * H / 8 + 255) / 256, 256>>>(lin_W, Wl, VOCAB * H / 8);

    // ---- encoder ----
    embed_enc_k<<<TENC * BATCH, 128>>>(x, enc_emb, Xe);
    init_all_k<<<BATCH, H>>>(h0f, h0h, hd0f, hd0h, dec_init);
    gemm_f16_k<<<dim3(TENC * BATCH / 128, 3 * H / 256), 512, GEMM_SMEM_BYTES>>>(
        Xe, We, enc_bih, Xi, 3 * H, DEMB, 0);
    gru_persistent_k<false><<<GRU_NCTA, 256, GRU_SMEM_BYTES>>>(
        h0f, h1f, h0h, h1h, enc_Whh, enc_bhh, Xi, nullptr, nullptr, TENC);
    float* efin = h0f;   // TENC even -> final state in h0f

    // ---- decoder precompute ----
    embed_dec_k<<<TDEC * BATCH, 128>>>(labels, bos, dec_emb, Xw);
    gemm_f16_k<<<dim3(TDEC * BATCH / 128, 3 * H / 256), 512, GEMM_SMEM_BYTES>>>(
        Xw, Wd, dec_bih, Xd, 3 * H, DEMB, 0);
    gemm_tf32_k<<<dim3(1, 24), 256>>>(efin, H, dec_Wih, DEMB + H, DEMB, ctx,
                                      BATCH, 3 * H, H);
    gru_persistent_k<true><<<GRU_NCTA, 256, GRU_SMEM_BYTES>>>(
        hd0f, hd1f, hd0h, hd1h, dec_Whh, dec_bhh, Xd, ctx, st, TDEC);

    // ---- logits ----
    gemm_f16_k<<<dim3(TDEC * BATCH / 128, VOCAB / 256), 512, GEMM_SMEM_BYTES>>>(
        st, Wl, lin_b, out, VOCAB, H, 1);
}